// round 2
// baseline (speedup 1.0000x reference)
#include <cuda_runtime.h>
#include <math.h>

#define BDIM 2
#define CDIM 8
#define NBINS 1024
#define WDIM 512
#define NHEADS 16
#define HD 64
#define BC (BDIM*CDIM)       /* 16  */
#define BCH (BC*NHEADS)      /* 256 */
#define FN_EPS 1e-5f

// ---------------- scratch (device globals; no allocation in kernel_launch) ---
__device__ float g_mean[BC*WDIM];
__device__ float g_rstd[BC*WDIM];
__device__ float g_z  [(size_t)BC*NBINS*WDIM];          // normalized activations (reused)
__device__ float g_y  [(size_t)BC*NBINS*WDIM];          // q-proj output (bc,g,w)
__device__ float g_qr [(size_t)BC*NBINS*WDIM];          // rotated q==k, (bch,w,d)
__device__ float g_v  [(size_t)BC*NBINS*WDIM];          // v, (bch,w,d)
__device__ float g_s  [(size_t)BCH*WDIM*WDIM];          // scores (bch,w,u)
__device__ float g_att[(size_t)BCH*WDIM*HD];            // attn out (bch,w,d)
__device__ float g_at [(size_t)BC*NBINS*WDIM];          // attn out back to (bc,g,w)
__device__ float g_x1 [(size_t)BC*NBINS*WDIM];          // x + attn
__device__ float g_h  [(size_t)BC*NBINS*4*WDIM];        // MLP hidden

// ---------------- frame-norm statistics: mean/rstd over BINS per (bc,w) -----
__global__ void stats_kernel(const float* __restrict__ x,
                             float* __restrict__ meanOut, float* __restrict__ rstdOut)
{
    int bc = blockIdx.x;
    int wl = threadIdx.x & 63;
    int fg = threadIdx.x >> 6;            // 0..3
    int w  = blockIdx.y * 64 + wl;
    const float* xb = x + (size_t)bc * NBINS * WDIM + w;
    float s = 0.f, sq = 0.f;
    for (int f = fg; f < NBINS; f += 4) {
        float v = xb[(size_t)f * WDIM];
        s += v; sq += v * v;
    }
    __shared__ float ss[4][64], sv[4][64];
    ss[fg][wl] = s; sv[fg][wl] = sq;
    __syncthreads();
    if (fg == 0) {
        s  = ss[0][wl] + ss[1][wl] + ss[2][wl] + ss[3][wl];
        sq = sv[0][wl] + sv[1][wl] + sv[2][wl] + sv[3][wl];
        float m   = s * (1.0f / NBINS);
        float var = sq * (1.0f / NBINS) - m * m;
        meanOut[bc * WDIM + w] = m;
        rstdOut[bc * WDIM + w] = rsqrtf(var + FN_EPS);
    }
}

// ---------------- apply norm elementwise ------------------------------------
__global__ void normalize_kernel(const float* __restrict__ x,
                                 const float* __restrict__ mean, const float* __restrict__ rstd,
                                 const float* __restrict__ wgt,  const float* __restrict__ bias,
                                 float* __restrict__ z)
{
    size_t idx = (size_t)blockIdx.x * 256 + threadIdx.x;
    int w  = (int)(idx & (WDIM - 1));
    int f  = (int)((idx >> 9) & (NBINS - 1));
    int bc = (int)(idx >> 19);
    int col = bc * WDIM + w;
    z[idx] = (x[idx] - mean[col]) * rstd[col] * wgt[f] + bias[f];
}

// ---------------- RoPE + transpose (bc,g,w) -> (bch,w,d); also emits V ------
__global__ void rope_kernel(const float* __restrict__ y, const float* __restrict__ freqs,
                            float* __restrict__ qr, float* __restrict__ v)
{
    __shared__ float tile[32][33];
    int bc = blockIdx.z;
    int g0 = blockIdx.y * 32;
    int w0 = blockIdx.x * 32;
    int tx = threadIdx.x, ty = threadIdx.y;
    const float* yb = y + (size_t)bc * NBINS * WDIM;
    #pragma unroll
    for (int r = 0; r < 4; r++) {
        int gl = ty + r * 8;
        tile[gl][tx] = yb[(size_t)(g0 + gl) * WDIM + w0 + tx];
    }
    __syncthreads();
    int h  = g0 / HD;
    int d0 = g0 % HD;                     // 0 (rope half) or 32 (passthrough)
    int d  = d0 + tx;
    float* qb = qr + (size_t)(bc * NHEADS + h) * WDIM * HD;
    float* vb = v  + (size_t)(bc * NHEADS + h) * WDIM * HD;
    float fr = (d0 == 0) ? freqs[d >> 1] : 0.f;
    #pragma unroll
    for (int r = 0; r < 4; r++) {
        int wl = ty + r * 8;
        int w  = w0 + wl;
        float val = tile[tx][wl];
        float o;
        if (d0 == 0) {
            float pv = tile[tx ^ 1][wl];
            float sn, cs;
            sincosf((float)w * fr, &sn, &cs);
            // even d: q[d]*cos - q[d+1]*sin ; odd d: q[d]*cos + q[d-1]*sin
            o = (d & 1) ? fmaf(val, cs,  pv * sn)
                        : fmaf(val, cs, -pv * sn);
        } else {
            o = val;
        }
        qb[(size_t)w * HD + d] = o;
        vb[(size_t)w * HD + d] = val;
    }
}

// ---------------- softmax over rows of 512 ----------------------------------
__global__ void softmax_kernel(float* __restrict__ s)
{
    int row  = blockIdx.x * 8 + (threadIdx.x >> 5);
    int lane = threadIdx.x & 31;
    float* p = s + (size_t)row * WDIM;
    float v[16];
    float mx = -1e30f;
    #pragma unroll
    for (int i = 0; i < 16; i++) { v[i] = p[lane + i * 32]; mx = fmaxf(mx, v[i]); }
    #pragma unroll
    for (int o = 16; o > 0; o >>= 1) mx = fmaxf(mx, __shfl_xor_sync(0xffffffffu, mx, o));
    float sum = 0.f;
    #pragma unroll
    for (int i = 0; i < 16; i++) { v[i] = expf(v[i] - mx); sum += v[i]; }
    #pragma unroll
    for (int o = 16; o > 0; o >>= 1) sum += __shfl_xor_sync(0xffffffffu, sum, o);
    float inv = 1.0f / sum;
    #pragma unroll
    for (int i = 0; i < 16; i++) p[lane + i * 32] = v[i] * inv;
}

// ---------------- (bch,w,d) -> (bc,g,w) transpose ---------------------------
__global__ void untranspose_kernel(const float* __restrict__ att, float* __restrict__ out)
{
    __shared__ float tile[32][33];
    int bc = blockIdx.z;
    int g0 = blockIdx.y * 32;
    int w0 = blockIdx.x * 32;
    int h  = g0 / HD;
    int d0 = g0 % HD;
    const float* ab = att + (size_t)(bc * NHEADS + h) * WDIM * HD;
    int tx = threadIdx.x, ty = threadIdx.y;
    #pragma unroll
    for (int r = 0; r < 4; r++) {
        int wl = ty + r * 8;
        tile[wl][tx] = ab[(size_t)(w0 + wl) * HD + d0 + tx];
    }
    __syncthreads();
    float* ob = out + (size_t)bc * NBINS * WDIM;
    #pragma unroll
    for (int r = 0; r < 4; r++) {
        int dl = ty + r * 8;
        ob[(size_t)(g0 + dl) * WDIM + w0 + tx] = tile[tx][dl];
    }
}

// ---------------- batched SGEMM: C = alpha * A @ B (+res | gelu) ------------
// A: MxK row-major (batch index = blockIdx.z % a_mod)
// B: KxN row-major, or NxK row-major when TRANSB (batch index = blockIdx.z)
// EPI: 0 = plain, 1 = + residual, 2 = gelu(exact)
template<bool TRANSB, int EPI>
__global__ void __launch_bounds__(256, 2)
sgemm_kernel(const float* __restrict__ Aall, const float* __restrict__ Ball,
             float* __restrict__ Call, const float* __restrict__ ResAll,
             int M, int N, int K, int a_mod, float alpha)
{
    const int batch = blockIdx.z;
    const float* A = Aall + (size_t)(batch % a_mod) * M * K;
    const float* B = Ball + (size_t)batch * K * N;
    float* C = Call + (size_t)batch * M * N;

    __shared__ float As[2][8][128];
    __shared__ float Bs[2][8][128];

    const int tid = threadIdx.x;
    const int m0 = blockIdx.y * 128;
    const int n0 = blockIdx.x * 128;

    const int aRow  = tid >> 1;
    const int aK    = (tid & 1) << 2;
    const int bK_nt = tid >> 5;
    const int bN_nt = (tid & 31) << 2;
    const int bN_t  = tid >> 1;
    const int bK_t  = (tid & 1) << 2;

    float4 aReg, bReg;

    auto ldA = [&](int kt) {
        aReg = *reinterpret_cast<const float4*>(A + (size_t)(m0 + aRow) * K + (kt << 3) + aK);
    };
    auto ldB = [&](int kt) {
        if (TRANSB) {
            int n = n0 + bN_t;
            if (n < N)
                bReg = *reinterpret_cast<const float4*>(B + (size_t)n * K + (kt << 3) + bK_t);
            else
                bReg = make_float4(0.f, 0.f, 0.f, 0.f);
        } else {
            int n = n0 + bN_nt;
            int k = (kt << 3) + bK_nt;
            if (n + 3 < N) {
                bReg = *reinterpret_cast<const float4*>(B + (size_t)k * N + n);
            } else {
                bReg.x = (n + 0 < N) ? B[(size_t)k * N + n + 0] : 0.f;
                bReg.y = (n + 1 < N) ? B[(size_t)k * N + n + 1] : 0.f;
                bReg.z = (n + 2 < N) ? B[(size_t)k * N + n + 2] : 0.f;
                bReg.w = (n + 3 < N) ? B[(size_t)k * N + n + 3] : 0.f;
            }
        }
    };
    auto stA = [&](int buf) {
        As[buf][aK + 0][aRow] = aReg.x;
        As[buf][aK + 1][aRow] = aReg.y;
        As[buf][aK + 2][aRow] = aReg.z;
        As[buf][aK + 3][aRow] = aReg.w;
    };
    auto stB = [&](int buf) {
        if (TRANSB) {
            Bs[buf][bK_t + 0][bN_t] = bReg.x;
            Bs[buf][bK_t + 1][bN_t] = bReg.y;
            Bs[buf][bK_t + 2][bN_t] = bReg.z;
            Bs[buf][bK_t + 3][bN_t] = bReg.w;
        } else {
            *reinterpret_cast<float4*>(&Bs[buf][bK_nt][bN_nt]) = bReg;
        }
    };

    float acc[8][8];
    #pragma unroll
    for (int i = 0; i < 8; i++)
        #pragma unroll
        for (int j = 0; j < 8; j++) acc[i][j] = 0.f;

    const int ty = tid >> 4;
    const int tx = tid & 15;
    const int nt = K >> 3;

    ldA(0); ldB(0);
    stA(0); stB(0);
    __syncthreads();
    int buf = 0;

    for (int t = 0; t < nt; t++) {
        if (t + 1 < nt) { ldA(t + 1); ldB(t + 1); }
        #pragma unroll
        for (int kk = 0; kk < 8; kk++) {
            float4 a0 = *reinterpret_cast<const float4*>(&As[buf][kk][ty << 3]);
            float4 a1 = *reinterpret_cast<const float4*>(&As[buf][kk][(ty << 3) + 4]);
            float4 b0 = *reinterpret_cast<const float4*>(&Bs[buf][kk][tx << 3]);
            float4 b1 = *reinterpret_cast<const float4*>(&Bs[buf][kk][(tx << 3) + 4]);
            float av[8] = {a0.x, a0.y, a0.z, a0.w, a1.x, a1.y, a1.z, a1.w};
            float bv[8] = {b0.x, b0.y, b0.z, b0.w, b1.x, b1.y, b1.z, b1.w};
            #pragma unroll
            for (int i = 0; i < 8; i++)
                #pragma unroll
                for (int j = 0; j < 8; j++)
                    acc[i][j] = fmaf(av[i], bv[j], acc[i][j]);
        }
        if (t + 1 < nt) {
            stA(buf ^ 1); stB(buf ^ 1);
            __syncthreads();
            buf ^= 1;
        }
    }

    const float* Res = (EPI == 1) ? (ResAll + (size_t)batch * M * N) : nullptr;
    #pragma unroll
    for (int i = 0; i < 8; i++) {
        int row = m0 + (ty << 3) + i;
        #pragma unroll
        for (int j = 0; j < 8; j++) {
            int col = n0 + (tx << 3) + j;
            if (col < N) {
                float vv = acc[i][j] * alpha;
                if (EPI == 1) vv += Res[(size_t)row * N + col];
                if (EPI == 2) vv = 0.5f * vv * (1.0f + erff(vv * 0.70710678118654752f));
                C[(size_t)row * N + col] = vv;
            }
        }
    }
}

// ---------------- launcher ----------------------------------------------------
extern "C" void kernel_launch(void* const* d_in, const int* in_sizes, int n_in,
                              void* d_out, int out_size)
{
    (void)in_sizes; (void)n_in; (void)out_size;
    const float* x      = (const float*)d_in[0];
    const float* n1w    = (const float*)d_in[1];
    const float* n1b    = (const float*)d_in[2];
    const float* freqs  = (const float*)d_in[3];
    const float* q_w    = (const float*)d_in[4];
    const float* out_w  = (const float*)d_in[5];
    const float* n2w    = (const float*)d_in[6];
    const float* n2b    = (const float*)d_in[7];
    const float* lin1_w = (const float*)d_in[8];
    const float* lin2_w = (const float*)d_in[9];
    float* out = (float*)d_out;

    float *p_mean, *p_rstd, *p_z, *p_y, *p_qr, *p_v, *p_s, *p_att, *p_at, *p_x1, *p_h;
    cudaGetSymbolAddress((void**)&p_mean, g_mean);
    cudaGetSymbolAddress((void**)&p_rstd, g_rstd);
    cudaGetSymbolAddress((void**)&p_z,   g_z);
    cudaGetSymbolAddress((void**)&p_y,   g_y);
    cudaGetSymbolAddress((void**)&p_qr,  g_qr);
    cudaGetSymbolAddress((void**)&p_v,   g_v);
    cudaGetSymbolAddress((void**)&p_s,   g_s);
    cudaGetSymbolAddress((void**)&p_att, g_att);
    cudaGetSymbolAddress((void**)&p_at,  g_at);
    cudaGetSymbolAddress((void**)&p_x1,  g_x1);
    cudaGetSymbolAddress((void**)&p_h,   g_h);

    dim3 statsGrid(BC, WDIM / 64);

    // norm1
    stats_kernel<<<statsGrid, 256>>>(x, p_mean, p_rstd);
    normalize_kernel<<<32768, 256>>>(x, p_mean, p_rstd, n1w, n1b, p_z);

    // q projection: y[bc] = q_w[c] @ z[bc]     (M=1024, N=512, K=1024)
    sgemm_kernel<false, 0><<<dim3(4, 8, BC), 256>>>(q_w, p_z, p_y, nullptr,
                                                    1024, 512, 1024, CDIM, 1.0f);

    // RoPE + head transpose (q == k; v = y)
    rope_kernel<<<dim3(16, 32, BC), dim3(32, 8)>>>(p_y, freqs, p_qr, p_v);

    // scores = QR @ QR^T / sqrt(1024)          (M=512, N=512, K=64, batched 256)
    sgemm_kernel<true, 0><<<dim3(4, 4, BCH), 256>>>(p_qr, p_qr, p_s, nullptr,
                                                    512, 512, 64, BCH, 0.03125f);

    // softmax over last dim
    softmax_kernel<<<BCH * WDIM / 8, 256>>>(p_s);

    // attn = P @ V                              (M=512, N=64, K=512, batched 256)
    sgemm_kernel<false, 0><<<dim3(1, 4, BCH), 256>>>(p_s, p_v, p_att, nullptr,
                                                     512, 64, 512, BCH, 1.0f);

    // back to (bc, g, w)
    untranspose_kernel<<<dim3(16, 32, BC), dim3(32, 8)>>>(p_att, p_at);

    // out projection + residual: x1 = x + out_w[c] @ at[bc]
    sgemm_kernel<false, 1><<<dim3(4, 8, BC), 256>>>(out_w, p_at, p_x1, x,
                                                    1024, 512, 1024, CDIM, 1.0f);

    // norm2
    stats_kernel<<<statsGrid, 256>>>(p_x1, p_mean, p_rstd);
    normalize_kernel<<<32768, 256>>>(p_x1, p_mean, p_rstd, n2w, n2b, p_z);

    // MLP lin1 + exact GELU                     (M=4096, N=512, K=1024)
    sgemm_kernel<false, 2><<<dim3(4, 32, BC), 256>>>(lin1_w, p_z, p_h, nullptr,
                                                     4096, 512, 1024, CDIM, 1.0f);

    // MLP lin2 + residual -> output             (M=1024, N=512, K=4096)
    sgemm_kernel<false, 1><<<dim3(4, 8, BC), 256>>>(lin2_w, p_h, out, p_x1,
                                                    1024, 512, 4096, CDIM, 1.0f);
}

// round 3
// speedup vs baseline: 2.8275x; 2.8275x over previous
#include <cuda_runtime.h>
#include <math.h>
#include <stdint.h>

#define BDIM 2
#define CDIM 8
#define NBINS 1024
#define WDIM 512
#define NHEADS 16
#define HD 64
#define BC (BDIM*CDIM)       /* 16  */
#define BCH (BC*NHEADS)      /* 256 */
#define FN_EPS 1e-5f

// ---------------- scratch (device globals; no allocation in kernel_launch) ---
__device__ float g_mean[BC*WDIM];
__device__ float g_rstd[BC*WDIM];
__device__ float g_z  [(size_t)BC*NBINS*WDIM];
__device__ float g_y  [(size_t)BC*NBINS*WDIM];
__device__ float g_qr [(size_t)BC*NBINS*WDIM];
__device__ float g_v  [(size_t)BC*NBINS*WDIM];
__device__ float g_s  [(size_t)BCH*WDIM*WDIM];
__device__ float g_att[(size_t)BCH*WDIM*HD];
__device__ float g_at [(size_t)BC*NBINS*WDIM];
__device__ float g_x1 [(size_t)BC*NBINS*WDIM];
__device__ float g_h  [(size_t)BC*NBINS*4*WDIM];

// ---------------- frame-norm statistics ------------------------------------
__global__ void stats_kernel(const float* __restrict__ x,
                             float* __restrict__ meanOut, float* __restrict__ rstdOut)
{
    int bc = blockIdx.x;
    int wl = threadIdx.x & 63;
    int fg = threadIdx.x >> 6;
    int w  = blockIdx.y * 64 + wl;
    const float* xb = x + (size_t)bc * NBINS * WDIM + w;
    float s = 0.f, sq = 0.f;
    for (int f = fg; f < NBINS; f += 4) {
        float v = xb[(size_t)f * WDIM];
        s += v; sq += v * v;
    }
    __shared__ float ss[4][64], sv[4][64];
    ss[fg][wl] = s; sv[fg][wl] = sq;
    __syncthreads();
    if (fg == 0) {
        s  = ss[0][wl] + ss[1][wl] + ss[2][wl] + ss[3][wl];
        sq = sv[0][wl] + sv[1][wl] + sv[2][wl] + sv[3][wl];
        float m   = s * (1.0f / NBINS);
        float var = sq * (1.0f / NBINS) - m * m;
        meanOut[bc * WDIM + w] = m;
        rstdOut[bc * WDIM + w] = rsqrtf(var + FN_EPS);
    }
}

// ---------------- apply norm elementwise ------------------------------------
__global__ void normalize_kernel(const float* __restrict__ x,
                                 const float* __restrict__ mean, const float* __restrict__ rstd,
                                 const float* __restrict__ wgt,  const float* __restrict__ bias,
                                 float* __restrict__ z)
{
    size_t idx = (size_t)blockIdx.x * 256 + threadIdx.x;
    int w  = (int)(idx & (WDIM - 1));
    int f  = (int)((idx >> 9) & (NBINS - 1));
    int bc = (int)(idx >> 19);
    int col = bc * WDIM + w;
    z[idx] = (x[idx] - mean[col]) * rstd[col] * wgt[f] + bias[f];
}

// ---------------- RoPE + transpose (bc,g,w) -> (bch,w,d); also emits V ------
__global__ void rope_kernel(const float* __restrict__ y, const float* __restrict__ freqs,
                            float* __restrict__ qr, float* __restrict__ v)
{
    __shared__ float tile[32][33];
    int bc = blockIdx.z;
    int g0 = blockIdx.y * 32;
    int w0 = blockIdx.x * 32;
    int tx = threadIdx.x, ty = threadIdx.y;
    const float* yb = y + (size_t)bc * NBINS * WDIM;
    #pragma unroll
    for (int r = 0; r < 4; r++) {
        int gl = ty + r * 8;
        tile[gl][tx] = yb[(size_t)(g0 + gl) * WDIM + w0 + tx];
    }
    __syncthreads();
    int h  = g0 / HD;
    int d0 = g0 % HD;
    int d  = d0 + tx;
    float* qb = qr + (size_t)(bc * NHEADS + h) * WDIM * HD;
    float* vb = v  + (size_t)(bc * NHEADS + h) * WDIM * HD;
    float fr = (d0 == 0) ? freqs[d >> 1] : 0.f;
    #pragma unroll
    for (int r = 0; r < 4; r++) {
        int wl = ty + r * 8;
        int w  = w0 + wl;
        float val = tile[tx][wl];
        float o;
        if (d0 == 0) {
            float pv = tile[tx ^ 1][wl];
            float sn, cs;
            sincosf((float)w * fr, &sn, &cs);
            o = (d & 1) ? fmaf(val, cs,  pv * sn)
                        : fmaf(val, cs, -pv * sn);
        } else {
            o = val;
        }
        qb[(size_t)w * HD + d] = o;
        vb[(size_t)w * HD + d] = val;
    }
}

// ---------------- softmax over rows of 512 ----------------------------------
__global__ void softmax_kernel(float* __restrict__ s)
{
    int row  = blockIdx.x * 8 + (threadIdx.x >> 5);
    int lane = threadIdx.x & 31;
    float* p = s + (size_t)row * WDIM;
    float v[16];
    float mx = -1e30f;
    #pragma unroll
    for (int i = 0; i < 16; i++) { v[i] = p[lane + i * 32]; mx = fmaxf(mx, v[i]); }
    #pragma unroll
    for (int o = 16; o > 0; o >>= 1) mx = fmaxf(mx, __shfl_xor_sync(0xffffffffu, mx, o));
    float sum = 0.f;
    #pragma unroll
    for (int i = 0; i < 16; i++) { v[i] = expf(v[i] - mx); sum += v[i]; }
    #pragma unroll
    for (int o = 16; o > 0; o >>= 1) sum += __shfl_xor_sync(0xffffffffu, sum, o);
    float inv = 1.0f / sum;
    #pragma unroll
    for (int i = 0; i < 16; i++) p[lane + i * 32] = v[i] * inv;
}

// ---------------- (bch,w,d) -> (bc,g,w) transpose ---------------------------
__global__ void untranspose_kernel(const float* __restrict__ att, float* __restrict__ out)
{
    __shared__ float tile[32][33];
    int bc = blockIdx.z;
    int g0 = blockIdx.y * 32;
    int w0 = blockIdx.x * 32;
    int h  = g0 / HD;
    int d0 = g0 % HD;
    const float* ab = att + (size_t)(bc * NHEADS + h) * WDIM * HD;
    int tx = threadIdx.x, ty = threadIdx.y;
    #pragma unroll
    for (int r = 0; r < 4; r++) {
        int wl = ty + r * 8;
        tile[wl][tx] = ab[(size_t)(w0 + wl) * HD + d0 + tx];
    }
    __syncthreads();
    float* ob = out + (size_t)bc * NBINS * WDIM;
    #pragma unroll
    for (int r = 0; r < 4; r++) {
        int dl = ty + r * 8;
        ob[(size_t)(g0 + dl) * WDIM + w0 + tx] = tile[tx][dl];
    }
}

// ================= TF32 tensor-core batched GEMM ============================
// C = alpha * A @ B (+ residual | gelu)
// A: MxK row-major (batch = blockIdx.z % a_mod)
// B: KxN row-major, or NxK row-major when TRANSB (batch = blockIdx.z)
// Block tile 128x128xBK16, 8 warps each 64x32 via m16n8k8 tf32 mma.
//
// Smem layouts (per double buffer):
//   As: [kk(2) stride 1028][m(128) stride 8][c*2+hi]   (LDS.64 pairs, conflict-free)
//   Bs: [kk(2) stride 1056][c(4) stride 264][hi(2) stride 132][n(128)]

#define AS_KK 1028
#define AS_BUF 2056
#define BS_C  264
#define BS_HI 132
#define BS_KK 1056
#define BS_BUF 2112

__device__ __forceinline__ float f2tf(float x) {
    uint32_t r;
    asm("cvt.rna.tf32.f32 %0, %1;" : "=r"(r) : "f"(x));
    return __uint_as_float(r);
}

__device__ __forceinline__ void mma_tf32(float c[4], uint32_t a0, uint32_t a1,
                                         uint32_t a2, uint32_t a3,
                                         uint32_t b0, uint32_t b1) {
    asm volatile(
        "mma.sync.aligned.m16n8k8.row.col.f32.tf32.tf32.f32 "
        "{%0,%1,%2,%3},{%4,%5,%6,%7},{%8,%9},{%0,%1,%2,%3};"
        : "+f"(c[0]), "+f"(c[1]), "+f"(c[2]), "+f"(c[3])
        : "r"(a0), "r"(a1), "r"(a2), "r"(a3), "r"(b0), "r"(b1));
}

template<bool TRANSB, int EPI>
__global__ void __launch_bounds__(256, 2)
tc_gemm(const float* __restrict__ Aall, const float* __restrict__ Ball,
        float* __restrict__ Call, const float* __restrict__ ResAll,
        int M, int N, int K, int a_mod, float alpha)
{
    __shared__ float As[2][AS_BUF];
    __shared__ float Bs[2][BS_BUF];

    const int batch = blockIdx.z;
    const float* A = Aall + (size_t)(batch % a_mod) * M * K;
    const float* B = Ball + (size_t)batch * (size_t)K * N;
    float* C = Call + (size_t)batch * (size_t)M * N;

    const int tid = threadIdx.x;
    const int m0 = blockIdx.y * 128;
    const int n0 = blockIdx.x * 128;
    const int nt = K >> 4;

    float4 ar[2], br[2];

    // -------- global loads (staged in regs) --------
    auto ldgA = [&](int t) {
        #pragma unroll
        for (int j = 0; j < 2; j++) {
            int p = tid + j * 256;
            int m = p >> 2, k4 = p & 3;
            ar[j] = *reinterpret_cast<const float4*>(
                A + (size_t)(m0 + m) * K + (t << 4) + (k4 << 2));
        }
    };
    auto ldgB = [&](int t) {
        #pragma unroll
        for (int j = 0; j < 2; j++) {
            if (TRANSB) {
                int p = tid + j * 256;
                int n = p >> 2, k4 = p & 3;
                br[j] = *reinterpret_cast<const float4*>(
                    B + (size_t)(n0 + n) * K + (t << 4) + (k4 << 2));
            } else {
                int k  = (tid >> 5) + j * 8;
                int n4 = tid & 31;
                int gn = n0 + (n4 << 2);
                if (gn + 3 < N)
                    br[j] = *reinterpret_cast<const float4*>(
                        B + (size_t)((t << 4) + k) * N + gn);
                else
                    br[j] = make_float4(0.f, 0.f, 0.f, 0.f);
            }
        }
    };
    // -------- smem stores (tf32-converted, permuted) --------
    auto stsA = [&](int buf) {
        #pragma unroll
        for (int j = 0; j < 2; j++) {
            int p = tid + j * 256;
            int m = p >> 2, k4 = p & 3;
            int kk = k4 >> 1, hi = k4 & 1;
            float* dst = &As[buf][kk * AS_KK + m * 8 + hi];
            dst[0] = f2tf(ar[j].x);
            dst[2] = f2tf(ar[j].y);
            dst[4] = f2tf(ar[j].z);
            dst[6] = f2tf(ar[j].w);
        }
    };
    auto stsB = [&](int buf) {
        #pragma unroll
        for (int j = 0; j < 2; j++) {
            if (TRANSB) {
                int p = tid + j * 256;
                int n = p >> 2, k4 = p & 3;
                int kk = k4 >> 1, hi = k4 & 1;
                float* dst = &Bs[buf][kk * BS_KK + hi * BS_HI + n];
                dst[0 * BS_C] = f2tf(br[j].x);
                dst[1 * BS_C] = f2tf(br[j].y);
                dst[2 * BS_C] = f2tf(br[j].z);
                dst[3 * BS_C] = f2tf(br[j].w);
            } else {
                int k  = (tid >> 5) + j * 8;
                int n4 = tid & 31;
                int kk = k >> 3, r = k & 7, c = r & 3, hi = r >> 2;
                float* dst = &Bs[buf][kk * BS_KK + c * BS_C + hi * BS_HI + (n4 << 2)];
                dst[0] = f2tf(br[j].x);
                dst[1] = f2tf(br[j].y);
                dst[2] = f2tf(br[j].z);
                dst[3] = f2tf(br[j].w);
            }
        }
    };

    float acc[4][4][4];
    #pragma unroll
    for (int i = 0; i < 4; i++)
        #pragma unroll
        for (int j = 0; j < 4; j++)
            #pragma unroll
            for (int q = 0; q < 4; q++) acc[i][j][q] = 0.f;

    const int lane = tid & 31;
    const int warp = tid >> 5;
    const int wm = (warp & 1) * 64;
    const int wn = (warp >> 1) * 32;
    const int lr = lane >> 2;   // 0..7
    const int lc = lane & 3;    // 0..3

    ldgA(0); ldgB(0);
    stsA(0); stsB(0);
    __syncthreads();
    int buf = 0;

    for (int t = 0; t < nt; t++) {
        if (t + 1 < nt) { ldgA(t + 1); ldgB(t + 1); }
        #pragma unroll
        for (int kk = 0; kk < 2; kk++) {
            const float* a_base = &As[buf][kk * AS_KK];
            const float* b_base = &Bs[buf][kk * BS_KK];
            uint32_t a[4][4], b[4][2];
            #pragma unroll
            for (int mt = 0; mt < 4; mt++) {
                int m = wm + mt * 16 + lr;
                float2 lo = *reinterpret_cast<const float2*>(a_base + m * 8 + lc * 2);
                float2 hi = *reinterpret_cast<const float2*>(a_base + (m + 8) * 8 + lc * 2);
                a[mt][0] = __float_as_uint(lo.x);
                a[mt][1] = __float_as_uint(hi.x);
                a[mt][2] = __float_as_uint(lo.y);
                a[mt][3] = __float_as_uint(hi.y);
            }
            #pragma unroll
            for (int ntile = 0; ntile < 4; ntile++) {
                int n = wn + ntile * 8 + lr;
                b[ntile][0] = __float_as_uint(b_base[lc * BS_C + n]);
                b[ntile][1] = __float_as_uint(b_base[lc * BS_C + BS_HI + n]);
            }
            #pragma unroll
            for (int mt = 0; mt < 4; mt++)
                #pragma unroll
                for (int ntile = 0; ntile < 4; ntile++)
                    mma_tf32(acc[mt][ntile],
                             a[mt][0], a[mt][1], a[mt][2], a[mt][3],
                             b[ntile][0], b[ntile][1]);
        }
        if (t + 1 < nt) {
            stsA(buf ^ 1); stsB(buf ^ 1);
            __syncthreads();
            buf ^= 1;
        }
    }

    // -------- epilogue --------
    const float* Res = (EPI == 1) ? (ResAll + (size_t)batch * (size_t)M * N) : nullptr;
    #pragma unroll
    for (int mt = 0; mt < 4; mt++) {
        #pragma unroll
        for (int ntile = 0; ntile < 4; ntile++) {
            int col = n0 + wn + ntile * 8 + lc * 2;
            if (col >= N) continue;
            #pragma unroll
            for (int half = 0; half < 2; half++) {
                int row = m0 + wm + mt * 16 + lr + half * 8;
                float v0 = acc[mt][ntile][half * 2 + 0] * alpha;
                float v1 = acc[mt][ntile][half * 2 + 1] * alpha;
                if (EPI == 1) {
                    v0 += Res[(size_t)row * N + col];
                    v1 += Res[(size_t)row * N + col + 1];
                }
                if (EPI == 2) {
                    v0 = 0.5f * v0 * (1.0f + erff(v0 * 0.70710678118654752f));
                    v1 = 0.5f * v1 * (1.0f + erff(v1 * 0.70710678118654752f));
                }
                float2 o = make_float2(v0, v1);
                *reinterpret_cast<float2*>(C + (size_t)row * N + col) = o;
            }
        }
    }
}

// ---------------- launcher ----------------------------------------------------
extern "C" void kernel_launch(void* const* d_in, const int* in_sizes, int n_in,
                              void* d_out, int out_size)
{
    (void)in_sizes; (void)n_in; (void)out_size;
    const float* x      = (const float*)d_in[0];
    const float* n1w    = (const float*)d_in[1];
    const float* n1b    = (const float*)d_in[2];
    const float* freqs  = (const float*)d_in[3];
    const float* q_w    = (const float*)d_in[4];
    const float* out_w  = (const float*)d_in[5];
    const float* n2w    = (const float*)d_in[6];
    const float* n2b    = (const float*)d_in[7];
    const float* lin1_w = (const float*)d_in[8];
    const float* lin2_w = (const float*)d_in[9];
    float* out = (float*)d_out;

    float *p_mean, *p_rstd, *p_z, *p_y, *p_qr, *p_v, *p_s, *p_att, *p_at, *p_x1, *p_h;
    cudaGetSymbolAddress((void**)&p_mean, g_mean);
    cudaGetSymbolAddress((void**)&p_rstd, g_rstd);
    cudaGetSymbolAddress((void**)&p_z,   g_z);
    cudaGetSymbolAddress((void**)&p_y,   g_y);
    cudaGetSymbolAddress((void**)&p_qr,  g_qr);
    cudaGetSymbolAddress((void**)&p_v,   g_v);
    cudaGetSymbolAddress((void**)&p_s,   g_s);
    cudaGetSymbolAddress((void**)&p_att, g_att);
    cudaGetSymbolAddress((void**)&p_at,  g_at);
    cudaGetSymbolAddress((void**)&p_x1,  g_x1);
    cudaGetSymbolAddress((void**)&p_h,   g_h);

    dim3 statsGrid(BC, WDIM / 64);

    // norm1
    stats_kernel<<<statsGrid, 256>>>(x, p_mean, p_rstd);
    normalize_kernel<<<32768, 256>>>(x, p_mean, p_rstd, n1w, n1b, p_z);

    // q projection: y[bc] = q_w[c] @ z[bc]     (M=1024, N=512, K=1024)
    tc_gemm<false, 0><<<dim3(4, 8, BC), 256>>>(q_w, p_z, p_y, nullptr,
                                               1024, 512, 1024, CDIM, 1.0f);

    // RoPE + head transpose (q == k; v = y)
    rope_kernel<<<dim3(16, 32, BC), dim3(32, 8)>>>(p_y, freqs, p_qr, p_v);

    // scores = QR @ QR^T / sqrt(1024)          (M=512, N=512, K=64, batched 256)
    tc_gemm<true, 0><<<dim3(4, 4, BCH), 256>>>(p_qr, p_qr, p_s, nullptr,
                                               512, 512, 64, BCH, 0.03125f);

    // softmax over last dim
    softmax_kernel<<<BCH * WDIM / 8, 256>>>(p_s);

    // attn = P @ V                              (M=512, N=64, K=512, batched 256)
    tc_gemm<false, 0><<<dim3(1, 4, BCH), 256>>>(p_s, p_v, p_att, nullptr,
                                                512, 64, 512, BCH, 1.0f);

    // back to (bc, g, w)
    untranspose_kernel<<<dim3(16, 32, BC), dim3(32, 8)>>>(p_att, p_at);

    // out projection + residual: x1 = x + out_w[c] @ at[bc]
    tc_gemm<false, 1><<<dim3(4, 8, BC), 256>>>(out_w, p_at, p_x1, x,
                                               1024, 512, 1024, CDIM, 1.0f);

    // norm2
    stats_kernel<<<statsGrid, 256>>>(p_x1, p_mean, p_rstd);
    normalize_kernel<<<32768, 256>>>(p_x1, p_mean, p_rstd, n2w, n2b, p_z);

    // MLP lin1 + exact GELU                     (M=4096, N=512, K=1024)
    tc_gemm<false, 2><<<dim3(4, 32, BC), 256>>>(lin1_w, p_z, p_h, nullptr,
                                                4096, 512, 1024, CDIM, 1.0f);

    // MLP lin2 + residual -> output             (M=1024, N=512, K=4096)
    tc_gemm<false, 1><<<dim3(4, 8, BC), 256>>>(lin2_w, p_h, out, p_x1,
                                               1024, 512, 4096, CDIM, 1.0f);
}

// round 4
// speedup vs baseline: 2.8354x; 1.0028x over previous
#include <cuda_runtime.h>
#include <math.h>
#include <stdint.h>

#define BDIM 2
#define CDIM 8
#define NBINS 1024
#define WDIM 512
#define NHEADS 16
#define HD 64
#define BC (BDIM*CDIM)       /* 16  */
#define BCH (BC*NHEADS)      /* 256 */
#define FN_EPS 1e-5f

// ---------------- scratch (device globals; no allocation in kernel_launch) ---
__device__ float g_mean[BC*WDIM];
__device__ float g_rstd[BC*WDIM];
__device__ float g_z  [(size_t)BC*NBINS*WDIM];
__device__ float g_y  [(size_t)BC*NBINS*WDIM];
__device__ float g_qr [(size_t)BC*NBINS*WDIM];
__device__ float g_v  [(size_t)BC*NBINS*WDIM];
__device__ float g_s  [(size_t)BCH*WDIM*WDIM];
__device__ float g_att[(size_t)BCH*WDIM*HD];
__device__ float g_at [(size_t)BC*NBINS*WDIM];
__device__ float g_x1 [(size_t)BC*NBINS*WDIM];
__device__ float g_h  [(size_t)BC*NBINS*4*WDIM];

// ---------------- frame-norm statistics ------------------------------------
__global__ void stats_kernel(const float* __restrict__ x,
                             float* __restrict__ meanOut, float* __restrict__ rstdOut)
{
    int bc = blockIdx.x;
    int wl = threadIdx.x & 63;
    int fg = threadIdx.x >> 6;
    int w  = blockIdx.y * 64 + wl;
    const float* xb = x + (size_t)bc * NBINS * WDIM + w;
    float s = 0.f, sq = 0.f;
    for (int f = fg; f < NBINS; f += 4) {
        float v = xb[(size_t)f * WDIM];
        s += v; sq += v * v;
    }
    __shared__ float ss[4][64], sv[4][64];
    ss[fg][wl] = s; sv[fg][wl] = sq;
    __syncthreads();
    if (fg == 0) {
        s  = ss[0][wl] + ss[1][wl] + ss[2][wl] + ss[3][wl];
        sq = sv[0][wl] + sv[1][wl] + sv[2][wl] + sv[3][wl];
        float m   = s * (1.0f / NBINS);
        float var = sq * (1.0f / NBINS) - m * m;
        meanOut[bc * WDIM + w] = m;
        rstdOut[bc * WDIM + w] = rsqrtf(var + FN_EPS);
    }
}

// ---------------- apply norm elementwise ------------------------------------
__global__ void normalize_kernel(const float* __restrict__ x,
                                 const float* __restrict__ mean, const float* __restrict__ rstd,
                                 const float* __restrict__ wgt,  const float* __restrict__ bias,
                                 float* __restrict__ z)
{
    size_t idx = (size_t)blockIdx.x * 256 + threadIdx.x;
    int w  = (int)(idx & (WDIM - 1));
    int f  = (int)((idx >> 9) & (NBINS - 1));
    int bc = (int)(idx >> 19);
    int col = bc * WDIM + w;
    z[idx] = (x[idx] - mean[col]) * rstd[col] * wgt[f] + bias[f];
}

// ---------------- RoPE + transpose (bc,g,w) -> (bch,w,d); also emits V ------
__global__ void rope_kernel(const float* __restrict__ y, const float* __restrict__ freqs,
                            float* __restrict__ qr, float* __restrict__ v)
{
    __shared__ float tile[32][33];
    int bc = blockIdx.z;
    int g0 = blockIdx.y * 32;
    int w0 = blockIdx.x * 32;
    int tx = threadIdx.x, ty = threadIdx.y;
    const float* yb = y + (size_t)bc * NBINS * WDIM;
    #pragma unroll
    for (int r = 0; r < 4; r++) {
        int gl = ty + r * 8;
        tile[gl][tx] = yb[(size_t)(g0 + gl) * WDIM + w0 + tx];
    }
    __syncthreads();
    int h  = g0 / HD;
    int d0 = g0 % HD;
    int d  = d0 + tx;
    float* qb = qr + (size_t)(bc * NHEADS + h) * WDIM * HD;
    float* vb = v  + (size_t)(bc * NHEADS + h) * WDIM * HD;
    float fr = (d0 == 0) ? freqs[d >> 1] : 0.f;
    #pragma unroll
    for (int r = 0; r < 4; r++) {
        int wl = ty + r * 8;
        int w  = w0 + wl;
        float val = tile[tx][wl];
        float o;
        if (d0 == 0) {
            float pv = tile[tx ^ 1][wl];
            float sn, cs;
            sincosf((float)w * fr, &sn, &cs);
            o = (d & 1) ? fmaf(val, cs,  pv * sn)
                        : fmaf(val, cs, -pv * sn);
        } else {
            o = val;
        }
        qb[(size_t)w * HD + d] = o;
        vb[(size_t)w * HD + d] = val;
    }
}

// ---------------- softmax over rows of 512 ----------------------------------
__global__ void softmax_kernel(float* __restrict__ s)
{
    int row  = blockIdx.x * 8 + (threadIdx.x >> 5);
    int lane = threadIdx.x & 31;
    float* p = s + (size_t)row * WDIM;
    float v[16];
    float mx = -1e30f;
    #pragma unroll
    for (int i = 0; i < 16; i++) { v[i] = p[lane + i * 32]; mx = fmaxf(mx, v[i]); }
    #pragma unroll
    for (int o = 16; o > 0; o >>= 1) mx = fmaxf(mx, __shfl_xor_sync(0xffffffffu, mx, o));
    float sum = 0.f;
    #pragma unroll
    for (int i = 0; i < 16; i++) { v[i] = expf(v[i] - mx); sum += v[i]; }
    #pragma unroll
    for (int o = 16; o > 0; o >>= 1) sum += __shfl_xor_sync(0xffffffffu, sum, o);
    float inv = 1.0f / sum;
    #pragma unroll
    for (int i = 0; i < 16; i++) p[lane + i * 32] = v[i] * inv;
}

// ---------------- (bch,w,d) -> (bc,g,w) transpose ---------------------------
__global__ void untranspose_kernel(const float* __restrict__ att, float* __restrict__ out)
{
    __shared__ float tile[32][33];
    int bc = blockIdx.z;
    int g0 = blockIdx.y * 32;
    int w0 = blockIdx.x * 32;
    int h  = g0 / HD;
    int d0 = g0 % HD;
    const float* ab = att + (size_t)(bc * NHEADS + h) * WDIM * HD;
    int tx = threadIdx.x, ty = threadIdx.y;
    #pragma unroll
    for (int r = 0; r < 4; r++) {
        int wl = ty + r * 8;
        tile[wl][tx] = ab[(size_t)(w0 + wl) * HD + d0 + tx];
    }
    __syncthreads();
    float* ob = out + (size_t)bc * NBINS * WDIM;
    #pragma unroll
    for (int r = 0; r < 4; r++) {
        int dl = ty + r * 8;
        ob[(size_t)(g0 + dl) * WDIM + w0 + tx] = tile[tx][dl];
    }
}

// ================= TF32 tensor-core batched GEMM ============================
// C = alpha * A @ B (+ residual | gelu)
// A: MxK row-major (batch = blockIdx.z % a_mod)
// B: KxN row-major, or NxK row-major when TRANSB (batch = blockIdx.z)
// Block tile 128x128xBK16, 8 warps each 64x32 via m16n8k8 tf32 mma.
//
// Smem layouts (per double buffer):
//   As: [kk(2) stride 1028][m(128) stride 8][c*2+hi]   (LDS.64 pairs, conflict-free)
//   Bs: [kk(2) stride 1056][c(4) stride 264][hi(2) stride 132][n(128)]

#define AS_KK 1028
#define AS_BUF 2056
#define BS_C  264
#define BS_HI 132
#define BS_KK 1056
#define BS_BUF 2112

__device__ __forceinline__ float f2tf(float x) {
    uint32_t r;
    asm("cvt.rna.tf32.f32 %0, %1;" : "=r"(r) : "f"(x));
    return __uint_as_float(r);
}

__device__ __forceinline__ void mma_tf32(float c[4], uint32_t a0, uint32_t a1,
                                         uint32_t a2, uint32_t a3,
                                         uint32_t b0, uint32_t b1) {
    asm volatile(
        "mma.sync.aligned.m16n8k8.row.col.f32.tf32.tf32.f32 "
        "{%0,%1,%2,%3},{%4,%5,%6,%7},{%8,%9},{%0,%1,%2,%3};"
        : "+f"(c[0]), "+f"(c[1]), "+f"(c[2]), "+f"(c[3])
        : "r"(a0), "r"(a1), "r"(a2), "r"(a3), "r"(b0), "r"(b1));
}

template<bool TRANSB, int EPI>
__global__ void __launch_bounds__(256, 2)
tc_gemm(const float* __restrict__ Aall, const float* __restrict__ Ball,
        float* __restrict__ Call, const float* __restrict__ ResAll,
        int M, int N, int K, int a_mod, float alpha)
{
    __shared__ float As[2][AS_BUF];
    __shared__ float Bs[2][BS_BUF];

    const int batch = blockIdx.z;
    const float* A = Aall + (size_t)(batch % a_mod) * M * K;
    const float* B = Ball + (size_t)batch * (size_t)K * N;
    float* C = Call + (size_t)batch * (size_t)M * N;

    const int tid = threadIdx.x;
    const int m0 = blockIdx.y * 128;
    const int n0 = blockIdx.x * 128;
    const int nt = K >> 4;

    float4 ar[2], br[2];

    // -------- global loads (staged in regs) --------
    auto ldgA = [&](int t) {
        #pragma unroll
        for (int j = 0; j < 2; j++) {
            int p = tid + j * 256;
            int m = p >> 2, k4 = p & 3;
            ar[j] = *reinterpret_cast<const float4*>(
                A + (size_t)(m0 + m) * K + (t << 4) + (k4 << 2));
        }
    };
    auto ldgB = [&](int t) {
        #pragma unroll
        for (int j = 0; j < 2; j++) {
            if (TRANSB) {
                int p = tid + j * 256;
                int n = p >> 2, k4 = p & 3;
                br[j] = *reinterpret_cast<const float4*>(
                    B + (size_t)(n0 + n) * K + (t << 4) + (k4 << 2));
            } else {
                int k  = (tid >> 5) + j * 8;
                int n4 = tid & 31;
                int gn = n0 + (n4 << 2);
                if (gn + 3 < N)
                    br[j] = *reinterpret_cast<const float4*>(
                        B + (size_t)((t << 4) + k) * N + gn);
                else
                    br[j] = make_float4(0.f, 0.f, 0.f, 0.f);
            }
        }
    };
    // -------- smem stores (tf32-converted, permuted) --------
    auto stsA = [&](int buf) {
        #pragma unroll
        for (int j = 0; j < 2; j++) {
            int p = tid + j * 256;
            int m = p >> 2, k4 = p & 3;
            int kk = k4 >> 1, hi = k4 & 1;
            float* dst = &As[buf][kk * AS_KK + m * 8 + hi];
            dst[0] = f2tf(ar[j].x);
            dst[2] = f2tf(ar[j].y);
            dst[4] = f2tf(ar[j].z);
            dst[6] = f2tf(ar[j].w);
        }
    };
    auto stsB = [&](int buf) {
        #pragma unroll
        for (int j = 0; j < 2; j++) {
            if (TRANSB) {
                int p = tid + j * 256;
                int n = p >> 2, k4 = p & 3;
                int kk = k4 >> 1, hi = k4 & 1;
                float* dst = &Bs[buf][kk * BS_KK + hi * BS_HI + n];
                dst[0 * BS_C] = f2tf(br[j].x);
                dst[1 * BS_C] = f2tf(br[j].y);
                dst[2 * BS_C] = f2tf(br[j].z);
                dst[3 * BS_C] = f2tf(br[j].w);
            } else {
                int k  = (tid >> 5) + j * 8;
                int n4 = tid & 31;
                int kk = k >> 3, r = k & 7, c = r & 3, hi = r >> 2;
                float* dst = &Bs[buf][kk * BS_KK + c * BS_C + hi * BS_HI + (n4 << 2)];
                dst[0] = f2tf(br[j].x);
                dst[1] = f2tf(br[j].y);
                dst[2] = f2tf(br[j].z);
                dst[3] = f2tf(br[j].w);
            }
        }
    };

    float acc[4][4][4];
    #pragma unroll
    for (int i = 0; i < 4; i++)
        #pragma unroll
        for (int j = 0; j < 4; j++)
            #pragma unroll
            for (int q = 0; q < 4; q++) acc[i][j][q] = 0.f;

    const int lane = tid & 31;
    const int warp = tid >> 5;
    const int wm = (warp & 1) * 64;
    const int wn = (warp >> 1) * 32;
    const int lr = lane >> 2;   // 0..7
    const int lc = lane & 3;    // 0..3

    ldgA(0); ldgB(0);
    stsA(0); stsB(0);
    __syncthreads();
    int buf = 0;

    for (int t = 0; t < nt; t++) {
        if (t + 1 < nt) { ldgA(t + 1); ldgB(t + 1); }
        #pragma unroll
        for (int kk = 0; kk < 2; kk++) {
            const float* a_base = &As[buf][kk * AS_KK];
            const float* b_base = &Bs[buf][kk * BS_KK];
            uint32_t a[4][4], b[4][2];
            #pragma unroll
            for (int mt = 0; mt < 4; mt++) {
                int m = wm + mt * 16 + lr;
                float2 lo = *reinterpret_cast<const float2*>(a_base + m * 8 + lc * 2);
                float2 hi = *reinterpret_cast<const float2*>(a_base + (m + 8) * 8 + lc * 2);
                a[mt][0] = __float_as_uint(lo.x);
                a[mt][1] = __float_as_uint(hi.x);
                a[mt][2] = __float_as_uint(lo.y);
                a[mt][3] = __float_as_uint(hi.y);
            }
            #pragma unroll
            for (int ntile = 0; ntile < 4; ntile++) {
                int n = wn + ntile * 8 + lr;
                b[ntile][0] = __float_as_uint(b_base[lc * BS_C + n]);
                b[ntile][1] = __float_as_uint(b_base[lc * BS_C + BS_HI + n]);
            }
            #pragma unroll
            for (int mt = 0; mt < 4; mt++)
                #pragma unroll
                for (int ntile = 0; ntile < 4; ntile++)
                    mma_tf32(acc[mt][ntile],
                             a[mt][0], a[mt][1], a[mt][2], a[mt][3],
                             b[ntile][0], b[ntile][1]);
        }
        if (t + 1 < nt) {
            stsA(buf ^ 1); stsB(buf ^ 1);
            __syncthreads();
            buf ^= 1;
        }
    }

    // -------- epilogue --------
    const float* Res = (EPI == 1) ? (ResAll + (size_t)batch * (size_t)M * N) : nullptr;
    #pragma unroll
    for (int mt = 0; mt < 4; mt++) {
        #pragma unroll
        for (int ntile = 0; ntile < 4; ntile++) {
            int col = n0 + wn + ntile * 8 + lc * 2;
            if (col >= N) continue;
            #pragma unroll
            for (int half = 0; half < 2; half++) {
                int row = m0 + wm + mt * 16 + lr + half * 8;
                float v0 = acc[mt][ntile][half * 2 + 0] * alpha;
                float v1 = acc[mt][ntile][half * 2 + 1] * alpha;
                if (EPI == 1) {
                    v0 += Res[(size_t)row * N + col];
                    v1 += Res[(size_t)row * N + col + 1];
                }
                if (EPI == 2) {
                    v0 = 0.5f * v0 * (1.0f + erff(v0 * 0.70710678118654752f));
                    v1 = 0.5f * v1 * (1.0f + erff(v1 * 0.70710678118654752f));
                }
                float2 o = make_float2(v0, v1);
                *reinterpret_cast<float2*>(C + (size_t)row * N + col) = o;
            }
        }
    }
}

// ---------------- launcher ----------------------------------------------------
extern "C" void kernel_launch(void* const* d_in, const int* in_sizes, int n_in,
                              void* d_out, int out_size)
{
    (void)in_sizes; (void)n_in; (void)out_size;
    const float* x      = (const float*)d_in[0];
    const float* n1w    = (const float*)d_in[1];
    const float* n1b    = (const float*)d_in[2];
    const float* freqs  = (const float*)d_in[3];
    const float* q_w    = (const float*)d_in[4];
    const float* out_w  = (const float*)d_in[5];
    const float* n2w    = (const float*)d_in[6];
    const float* n2b    = (const float*)d_in[7];
    const float* lin1_w = (const float*)d_in[8];
    const float* lin2_w = (const float*)d_in[9];
    float* out = (float*)d_out;

    float *p_mean, *p_rstd, *p_z, *p_y, *p_qr, *p_v, *p_s, *p_att, *p_at, *p_x1, *p_h;
    cudaGetSymbolAddress((void**)&p_mean, g_mean);
    cudaGetSymbolAddress((void**)&p_rstd, g_rstd);
    cudaGetSymbolAddress((void**)&p_z,   g_z);
    cudaGetSymbolAddress((void**)&p_y,   g_y);
    cudaGetSymbolAddress((void**)&p_qr,  g_qr);
    cudaGetSymbolAddress((void**)&p_v,   g_v);
    cudaGetSymbolAddress((void**)&p_s,   g_s);
    cudaGetSymbolAddress((void**)&p_att, g_att);
    cudaGetSymbolAddress((void**)&p_at,  g_at);
    cudaGetSymbolAddress((void**)&p_x1,  g_x1);
    cudaGetSymbolAddress((void**)&p_h,   g_h);

    dim3 statsGrid(BC, WDIM / 64);

    // norm1
    stats_kernel<<<statsGrid, 256>>>(x, p_mean, p_rstd);
    normalize_kernel<<<32768, 256>>>(x, p_mean, p_rstd, n1w, n1b, p_z);

    // q projection: y[bc] = q_w[c] @ z[bc]     (M=1024, N=512, K=1024)
    tc_gemm<false, 0><<<dim3(4, 8, BC), 256>>>(q_w, p_z, p_y, nullptr,
                                               1024, 512, 1024, CDIM, 1.0f);

    // RoPE + head transpose (q == k; v = y)
    rope_kernel<<<dim3(16, 32, BC), dim3(32, 8)>>>(p_y, freqs, p_qr, p_v);

    // scores = QR @ QR^T / sqrt(1024)          (M=512, N=512, K=64, batched 256)
    tc_gemm<true, 0><<<dim3(4, 4, BCH), 256>>>(p_qr, p_qr, p_s, nullptr,
                                               512, 512, 64, BCH, 0.03125f);

    // softmax over last dim
    softmax_kernel<<<BCH * WDIM / 8, 256>>>(p_s);

    // attn = P @ V                              (M=512, N=64, K=512, batched 256)
    tc_gemm<false, 0><<<dim3(1, 4, BCH), 256>>>(p_s, p_v, p_att, nullptr,
                                                512, 64, 512, BCH, 1.0f);

    // back to (bc, g, w)
    untranspose_kernel<<<dim3(16, 32, BC), dim3(32, 8)>>>(p_att, p_at);

    // out projection + residual: x1 = x + out_w[c] @ at[bc]
    tc_gemm<false, 1><<<dim3(4, 8, BC), 256>>>(out_w, p_at, p_x1, x,
                                               1024, 512, 1024, CDIM, 1.0f);

    // norm2
    stats_kernel<<<statsGrid, 256>>>(p_x1, p_mean, p_rstd);
    normalize_kernel<<<32768, 256>>>(p_x1, p_mean, p_rstd, n2w, n2b, p_z);

    // MLP lin1 + exact GELU                     (M=4096, N=512, K=1024)
    tc_gemm<false, 2><<<dim3(4, 32, BC), 256>>>(lin1_w, p_z, p_h, nullptr,
                                                4096, 512, 1024, CDIM, 1.0f);

    // MLP lin2 + residual -> output             (M=1024, N=512, K=4096)
    tc_gemm<false, 1><<<dim3(4, 8, BC), 256>>>(lin2_w, p_h, out, p_x1,
                                               1024, 512, 4096, CDIM, 1.0f);
}

// round 5
// speedup vs baseline: 3.5268x; 1.2439x over previous
#include <cuda_runtime.h>
#include <cuda_fp16.h>
#include <math.h>
#include <stdint.h>

#define BDIM 2
#define CDIM 8
#define NBINS 1024
#define WDIM 512
#define NHEADS 16
#define HD 64
#define BC (BDIM*CDIM)       /* 16  */
#define BCH (BC*NHEADS)      /* 256 */
#define FN_EPS 1e-5f

// ---------------- scratch (device globals; no allocation in kernel_launch) ---
__device__ float g_mean[BC*WDIM];
__device__ float g_rstd[BC*WDIM];
__device__ float g_z  [(size_t)BC*NBINS*WDIM];
__device__ float g_y  [(size_t)BC*NBINS*WDIM];
__device__ float g_qr [(size_t)BC*NBINS*WDIM];
__device__ float g_v  [(size_t)BC*NBINS*WDIM];
__device__ float g_s  [(size_t)BCH*WDIM*WDIM];
__device__ float g_att[(size_t)BCH*WDIM*HD];
__device__ float g_at [(size_t)BC*NBINS*WDIM];
__device__ float g_x1 [(size_t)BC*NBINS*WDIM];
__device__ float g_h  [(size_t)BC*NBINS*4*WDIM];

// ---------------- frame-norm statistics ------------------------------------
__global__ void stats_kernel(const float* __restrict__ x,
                             float* __restrict__ meanOut, float* __restrict__ rstdOut)
{
    int bc = blockIdx.x;
    int wl = threadIdx.x & 63;
    int fg = threadIdx.x >> 6;
    int w  = blockIdx.y * 64 + wl;
    const float* xb = x + (size_t)bc * NBINS * WDIM + w;
    float s = 0.f, sq = 0.f;
    for (int f = fg; f < NBINS; f += 4) {
        float v = xb[(size_t)f * WDIM];
        s += v; sq += v * v;
    }
    __shared__ float ss[4][64], sv[4][64];
    ss[fg][wl] = s; sv[fg][wl] = sq;
    __syncthreads();
    if (fg == 0) {
        s  = ss[0][wl] + ss[1][wl] + ss[2][wl] + ss[3][wl];
        sq = sv[0][wl] + sv[1][wl] + sv[2][wl] + sv[3][wl];
        float m   = s * (1.0f / NBINS);
        float var = sq * (1.0f / NBINS) - m * m;
        meanOut[bc * WDIM + w] = m;
        rstdOut[bc * WDIM + w] = rsqrtf(var + FN_EPS);
    }
}

// ---------------- apply norm elementwise ------------------------------------
__global__ void normalize_kernel(const float* __restrict__ x,
                                 const float* __restrict__ mean, const float* __restrict__ rstd,
                                 const float* __restrict__ wgt,  const float* __restrict__ bias,
                                 float* __restrict__ z)
{
    size_t idx = (size_t)blockIdx.x * 256 + threadIdx.x;
    int w  = (int)(idx & (WDIM - 1));
    int f  = (int)((idx >> 9) & (NBINS - 1));
    int bc = (int)(idx >> 19);
    int col = bc * WDIM + w;
    z[idx] = (x[idx] - mean[col]) * rstd[col] * wgt[f] + bias[f];
}

// ---------------- RoPE + transpose (bc,g,w) -> (bch,w,d); also emits V ------
__global__ void rope_kernel(const float* __restrict__ y, const float* __restrict__ freqs,
                            float* __restrict__ qr, float* __restrict__ v)
{
    __shared__ float tile[32][33];
    int bc = blockIdx.z;
    int g0 = blockIdx.y * 32;
    int w0 = blockIdx.x * 32;
    int tx = threadIdx.x, ty = threadIdx.y;
    const float* yb = y + (size_t)bc * NBINS * WDIM;
    #pragma unroll
    for (int r = 0; r < 4; r++) {
        int gl = ty + r * 8;
        tile[gl][tx] = yb[(size_t)(g0 + gl) * WDIM + w0 + tx];
    }
    __syncthreads();
    int h  = g0 / HD;
    int d0 = g0 % HD;
    int d  = d0 + tx;
    float* qb = qr + (size_t)(bc * NHEADS + h) * WDIM * HD;
    float* vb = v  + (size_t)(bc * NHEADS + h) * WDIM * HD;
    float fr = (d0 == 0) ? freqs[d >> 1] : 0.f;
    #pragma unroll
    for (int r = 0; r < 4; r++) {
        int wl = ty + r * 8;
        int w  = w0 + wl;
        float val = tile[tx][wl];
        float o;
        if (d0 == 0) {
            float pv = tile[tx ^ 1][wl];
            float sn, cs;
            sincosf((float)w * fr, &sn, &cs);
            o = (d & 1) ? fmaf(val, cs,  pv * sn)
                        : fmaf(val, cs, -pv * sn);
        } else {
            o = val;
        }
        qb[(size_t)w * HD + d] = o;
        vb[(size_t)w * HD + d] = val;
    }
}

// ---------------- softmax over rows of 512 ----------------------------------
__global__ void softmax_kernel(float* __restrict__ s)
{
    int row  = blockIdx.x * 8 + (threadIdx.x >> 5);
    int lane = threadIdx.x & 31;
    float* p = s + (size_t)row * WDIM;
    float v[16];
    float mx = -1e30f;
    #pragma unroll
    for (int i = 0; i < 16; i++) { v[i] = p[lane + i * 32]; mx = fmaxf(mx, v[i]); }
    #pragma unroll
    for (int o = 16; o > 0; o >>= 1) mx = fmaxf(mx, __shfl_xor_sync(0xffffffffu, mx, o));
    float sum = 0.f;
    #pragma unroll
    for (int i = 0; i < 16; i++) { v[i] = expf(v[i] - mx); sum += v[i]; }
    #pragma unroll
    for (int o = 16; o > 0; o >>= 1) sum += __shfl_xor_sync(0xffffffffu, sum, o);
    float inv = 1.0f / sum;
    #pragma unroll
    for (int i = 0; i < 16; i++) p[lane + i * 32] = v[i] * inv;
}

// ---------------- (bch,w,d) -> (bc,g,w) transpose ---------------------------
__global__ void untranspose_kernel(const float* __restrict__ att, float* __restrict__ out)
{
    __shared__ float tile[32][33];
    int bc = blockIdx.z;
    int g0 = blockIdx.y * 32;
    int w0 = blockIdx.x * 32;
    int h  = g0 / HD;
    int d0 = g0 % HD;
    const float* ab = att + (size_t)(bc * NHEADS + h) * WDIM * HD;
    int tx = threadIdx.x, ty = threadIdx.y;
    #pragma unroll
    for (int r = 0; r < 4; r++) {
        int wl = ty + r * 8;
        tile[wl][tx] = ab[(size_t)(w0 + wl) * HD + d0 + tx];
    }
    __syncthreads();
    float* ob = out + (size_t)bc * NBINS * WDIM;
    #pragma unroll
    for (int r = 0; r < 4; r++) {
        int dl = ty + r * 8;
        ob[(size_t)(g0 + dl) * WDIM + w0 + tx] = tile[tx][dl];
    }
}

// ================= FP16 tensor-core batched GEMM ============================
// C = alpha * A @ B (+ residual | gelu), fp32 in/out, fp16 mma (f32 accum).
// A: MxK row-major (batch = blockIdx.z % a_mod)
// B: KxN row-major, or NxK row-major when TRANSB (batch = blockIdx.z)
// Block tile 128x128x32 (BK=32 = 2 k16 slabs), 8 warps each 64x32 via
// m16n8k16 fp16 mma.
//
// Smem word layout (uint32 = packed half2 of k-pair):
//   addr(row, k) = kk*1024 + row*8 + 2*c + h     (A; row = m)
//   addr(row, k) = kk*1024 + row*8 + 2*(c ^ ((row>>2)&3)) + h  (B; row = n)
// where kk = k>>4, h = (k>>3)&1, c = (k&7)>>1.
// Fragment fetch is one LDS.64 per (row, lc): words (2c+h=0,1) = (b0,b1)/(a0,a2).

__device__ __forceinline__ uint32_t packh2(float x, float y) {
    __half2 h = __floats2half2_rn(x, y);
    return *reinterpret_cast<uint32_t*>(&h);
}

__device__ __forceinline__ void mma_f16(float c[4], uint32_t a0, uint32_t a1,
                                        uint32_t a2, uint32_t a3,
                                        uint32_t b0, uint32_t b1) {
    asm volatile(
        "mma.sync.aligned.m16n8k16.row.col.f32.f16.f16.f32 "
        "{%0,%1,%2,%3},{%4,%5,%6,%7},{%8,%9},{%0,%1,%2,%3};"
        : "+f"(c[0]), "+f"(c[1]), "+f"(c[2]), "+f"(c[3])
        : "r"(a0), "r"(a1), "r"(a2), "r"(a3), "r"(b0), "r"(b1));
}

#define BSWZ(n, c) ((c) ^ (((n) >> 2) & 3))

template<bool TRANSB, int EPI>
__global__ void __launch_bounds__(256, 2)
tc_gemm(const float* __restrict__ Aall, const float* __restrict__ Ball,
        float* __restrict__ Call, const float* __restrict__ ResAll,
        int M, int N, int K, int a_mod, float alpha)
{
    __shared__ uint32_t As[2][2048];   // [buf][kk*1024 + m*8 + word]
    __shared__ uint32_t Bs[2][2048];   // [buf][kk*1024 + n*8 + word]

    const int batch = blockIdx.z;
    const float* A = Aall + (size_t)(batch % a_mod) * M * K;
    const float* B = Ball + (size_t)batch * (size_t)K * N;
    float* C = Call + (size_t)batch * (size_t)M * N;

    const int tid = threadIdx.x;
    const int m0 = blockIdx.y * 128;
    const int n0 = blockIdx.x * 128;
    const int nt = K >> 5;

    float4 ar[4];      // A staging: 4 float4 (128x32 tile / 256 thr)
    float4 br[4];      // B staging

    auto ldgA = [&](int t) {
        #pragma unroll
        for (int j = 0; j < 4; j++) {
            int p = tid + j * 256;          // 0..1023
            int m = p >> 3, k4 = p & 7;     // k = 4*k4
            ar[j] = *reinterpret_cast<const float4*>(
                A + (size_t)(m0 + m) * K + (t << 5) + (k4 << 2));
        }
    };
    auto stsA = [&](int buf) {
        #pragma unroll
        for (int j = 0; j < 4; j++) {
            int p = tid + j * 256;
            int m = p >> 3, k4 = p & 7;
            int k  = k4 << 2;
            int kk = k >> 4;
            int kl = k & 15;
            int h  = kl >> 3;
            int c  = (kl & 7) >> 1;
            uint32_t* dst = &As[buf][kk * 1024 + m * 8 + 2 * c + h];
            dst[0] = packh2(ar[j].x, ar[j].y);
            dst[2] = packh2(ar[j].z, ar[j].w);
        }
    };
    auto ldgB = [&](int t) {
        if (TRANSB) {
            #pragma unroll
            for (int j = 0; j < 4; j++) {
                int p = tid + j * 256;
                int n = p >> 3, k4 = p & 7;
                br[j] = *reinterpret_cast<const float4*>(
                    B + (size_t)(n0 + n) * K + (t << 5) + (k4 << 2));
            }
        } else {
            #pragma unroll
            for (int j = 0; j < 2; j++) {
                int it = tid + j * 256;     // 0..511
                int kp = it >> 5;           // 0..15 (k-pair)
                int n4 = it & 31;
                int gn = n0 + (n4 << 2);
                if (gn < N) {
                    const float* base = B + (size_t)((t << 5) + (kp << 1)) * N + gn;
                    br[2 * j + 0] = *reinterpret_cast<const float4*>(base);
                    br[2 * j + 1] = *reinterpret_cast<const float4*>(base + N);
                } else {
                    br[2 * j + 0] = make_float4(0.f, 0.f, 0.f, 0.f);
                    br[2 * j + 1] = make_float4(0.f, 0.f, 0.f, 0.f);
                }
            }
        }
    };
    auto stsB = [&](int buf) {
        if (TRANSB) {
            #pragma unroll
            for (int j = 0; j < 4; j++) {
                int p = tid + j * 256;
                int n = p >> 3, k4 = p & 7;
                int k  = k4 << 2;
                int kk = k >> 4;
                int kl = k & 15;
                int h  = kl >> 3;
                int c  = (kl & 7) >> 1;
                uint32_t* rowp = &Bs[buf][kk * 1024 + n * 8];
                rowp[2 * BSWZ(n, c)     + h] = packh2(br[j].x, br[j].y);
                rowp[2 * BSWZ(n, c + 1) + h] = packh2(br[j].z, br[j].w);
            }
        } else {
            #pragma unroll
            for (int j = 0; j < 2; j++) {
                int it = tid + j * 256;
                int kp = it >> 5;
                int n4 = it & 31;
                int kk = kp >> 3;
                int h  = (kp >> 2) & 1;
                int c  = kp & 3;
                float r0[4] = {br[2*j].x, br[2*j].y, br[2*j].z, br[2*j].w};
                float r1[4] = {br[2*j+1].x, br[2*j+1].y, br[2*j+1].z, br[2*j+1].w};
                #pragma unroll
                for (int i = 0; i < 4; i++) {
                    int n = (n4 << 2) + i;
                    Bs[buf][kk * 1024 + n * 8 + 2 * BSWZ(n, c) + h] =
                        packh2(r0[i], r1[i]);
                }
            }
        }
    };

    float acc[4][4][4];
    #pragma unroll
    for (int i = 0; i < 4; i++)
        #pragma unroll
        for (int j = 0; j < 4; j++)
            #pragma unroll
            for (int q = 0; q < 4; q++) acc[i][j][q] = 0.f;

    const int lane = tid & 31;
    const int warp = tid >> 5;
    const int wm = (warp & 1) * 64;
    const int wn = (warp >> 1) * 32;
    const int lr = lane >> 2;   // 0..7
    const int lc = lane & 3;    // 0..3

    ldgA(0); ldgB(0);
    stsA(0); stsB(0);
    __syncthreads();
    int buf = 0;

    for (int t = 0; t < nt; t++) {
        if (t + 1 < nt) { ldgA(t + 1); ldgB(t + 1); }
        #pragma unroll
        for (int kk = 0; kk < 2; kk++) {
            const uint32_t* a_base = &As[buf][kk * 1024];
            const uint32_t* b_base = &Bs[buf][kk * 1024];
            uint32_t a[4][4];
            uint2 b[4];
            #pragma unroll
            for (int mt = 0; mt < 4; mt++) {
                int m = wm + mt * 16 + lr;
                uint2 lo = *reinterpret_cast<const uint2*>(a_base + m * 8 + 2 * lc);
                uint2 hi = *reinterpret_cast<const uint2*>(a_base + (m + 8) * 8 + 2 * lc);
                a[mt][0] = lo.x;   // (m,   k lo8)
                a[mt][1] = hi.x;   // (m+8, k lo8)
                a[mt][2] = lo.y;   // (m,   k hi8)
                a[mt][3] = hi.y;   // (m+8, k hi8)
            }
            #pragma unroll
            for (int ntile = 0; ntile < 4; ntile++) {
                int n = wn + ntile * 8 + lr;
                b[ntile] = *reinterpret_cast<const uint2*>(
                    b_base + n * 8 + 2 * BSWZ(n, lc));
            }
            #pragma unroll
            for (int mt = 0; mt < 4; mt++)
                #pragma unroll
                for (int ntile = 0; ntile < 4; ntile++)
                    mma_f16(acc[mt][ntile],
                            a[mt][0], a[mt][1], a[mt][2], a[mt][3],
                            b[ntile].x, b[ntile].y);
        }
        if (t + 1 < nt) {
            stsA(buf ^ 1); stsB(buf ^ 1);
            __syncthreads();
            buf ^= 1;
        }
    }

    // -------- epilogue --------
    const float* Res = (EPI == 1) ? (ResAll + (size_t)batch * (size_t)M * N) : nullptr;
    #pragma unroll
    for (int mt = 0; mt < 4; mt++) {
        #pragma unroll
        for (int ntile = 0; ntile < 4; ntile++) {
            int col = n0 + wn + ntile * 8 + lc * 2;
            if (col >= N) continue;
            #pragma unroll
            for (int half = 0; half < 2; half++) {
                int row = m0 + wm + mt * 16 + lr + half * 8;
                float v0 = acc[mt][ntile][half * 2 + 0] * alpha;
                float v1 = acc[mt][ntile][half * 2 + 1] * alpha;
                if (EPI == 1) {
                    v0 += Res[(size_t)row * N + col];
                    v1 += Res[(size_t)row * N + col + 1];
                }
                if (EPI == 2) {
                    v0 = 0.5f * v0 * (1.0f + erff(v0 * 0.70710678118654752f));
                    v1 = 0.5f * v1 * (1.0f + erff(v1 * 0.70710678118654752f));
                }
                float2 o = make_float2(v0, v1);
                *reinterpret_cast<float2*>(C + (size_t)row * N + col) = o;
            }
        }
    }
}

// ---------------- launcher ----------------------------------------------------
extern "C" void kernel_launch(void* const* d_in, const int* in_sizes, int n_in,
                              void* d_out, int out_size)
{
    (void)in_sizes; (void)n_in; (void)out_size;
    const float* x      = (const float*)d_in[0];
    const float* n1w    = (const float*)d_in[1];
    const float* n1b    = (const float*)d_in[2];
    const float* freqs  = (const float*)d_in[3];
    const float* q_w    = (const float*)d_in[4];
    const float* out_w  = (const float*)d_in[5];
    const float* n2w    = (const float*)d_in[6];
    const float* n2b    = (const float*)d_in[7];
    const float* lin1_w = (const float*)d_in[8];
    const float* lin2_w = (const float*)d_in[9];
    float* out = (float*)d_out;

    float *p_mean, *p_rstd, *p_z, *p_y, *p_qr, *p_v, *p_s, *p_att, *p_at, *p_x1, *p_h;
    cudaGetSymbolAddress((void**)&p_mean, g_mean);
    cudaGetSymbolAddress((void**)&p_rstd, g_rstd);
    cudaGetSymbolAddress((void**)&p_z,   g_z);
    cudaGetSymbolAddress((void**)&p_y,   g_y);
    cudaGetSymbolAddress((void**)&p_qr,  g_qr);
    cudaGetSymbolAddress((void**)&p_v,   g_v);
    cudaGetSymbolAddress((void**)&p_s,   g_s);
    cudaGetSymbolAddress((void**)&p_att, g_att);
    cudaGetSymbolAddress((void**)&p_at,  g_at);
    cudaGetSymbolAddress((void**)&p_x1,  g_x1);
    cudaGetSymbolAddress((void**)&p_h,   g_h);

    dim3 statsGrid(BC, WDIM / 64);

    // norm1
    stats_kernel<<<statsGrid, 256>>>(x, p_mean, p_rstd);
    normalize_kernel<<<32768, 256>>>(x, p_mean, p_rstd, n1w, n1b, p_z);

    // q projection: y[bc] = q_w[c] @ z[bc]     (M=1024, N=512, K=1024)
    tc_gemm<false, 0><<<dim3(4, 8, BC), 256>>>(q_w, p_z, p_y, nullptr,
                                               1024, 512, 1024, CDIM, 1.0f);

    // RoPE + head transpose (q == k; v = y)
    rope_kernel<<<dim3(16, 32, BC), dim3(32, 8)>>>(p_y, freqs, p_qr, p_v);

    // scores = QR @ QR^T / sqrt(1024)          (M=512, N=512, K=64, batched 256)
    tc_gemm<true, 0><<<dim3(4, 4, BCH), 256>>>(p_qr, p_qr, p_s, nullptr,
                                               512, 512, 64, BCH, 0.03125f);

    // softmax over last dim
    softmax_kernel<<<BCH * WDIM / 8, 256>>>(p_s);

    // attn = P @ V                              (M=512, N=64, K=512, batched 256)
    tc_gemm<false, 0><<<dim3(1, 4, BCH), 256>>>(p_s, p_v, p_att, nullptr,
                                                512, 64, 512, BCH, 1.0f);

    // back to (bc, g, w)
    untranspose_kernel<<<dim3(16, 32, BC), dim3(32, 8)>>>(p_att, p_at);

    // out projection + residual: x1 = x + out_w[c] @ at[bc]
    tc_gemm<false, 1><<<dim3(4, 8, BC), 256>>>(out_w, p_at, p_x1, x,
                                               1024, 512, 1024, CDIM, 1.0f);

    // norm2
    stats_kernel<<<statsGrid, 256>>>(p_x1, p_mean, p_rstd);
    normalize_kernel<<<32768, 256>>>(p_x1, p_mean, p_rstd, n2w, n2b, p_z);

    // MLP lin1 + exact GELU                     (M=4096, N=512, K=1024)
    tc_gemm<false, 2><<<dim3(4, 32, BC), 256>>>(lin1_w, p_z, p_h, nullptr,
                                                4096, 512, 1024, CDIM, 1.0f);

    // MLP lin2 + residual -> output             (M=1024, N=512, K=4096)
    tc_gemm<false, 1><<<dim3(4, 8, BC), 256>>>(lin2_w, p_h, out, p_x1,
                                               1024, 512, 4096, CDIM, 1.0f);
}

// round 6
// speedup vs baseline: 5.4966x; 1.5585x over previous
#include <cuda_runtime.h>
#include <cuda_fp16.h>
#include <math.h>
#include <stdint.h>

#define BDIM 2
#define CDIM 8
#define NBINS 1024
#define WDIM 512
#define NHEADS 16
#define HD 64
#define BC (BDIM*CDIM)       /* 16  */
#define BCH (BC*NHEADS)      /* 256 */
#define FN_EPS 1e-5f

// ---------------- scratch (device globals) -----------------------------------
__device__ float  g_mean[BC*WDIM];
__device__ float  g_rstd[BC*WDIM];
__device__ float  g_y  [(size_t)BC*NBINS*WDIM];           // q-proj out (fp32, feeds rope)
__device__ float  g_s  [(size_t)BCH*WDIM*WDIM];           // scores fp32
__device__ float  g_att[(size_t)BCH*WDIM*HD];             // attn out fp32
__device__ float  g_x1 [(size_t)BC*NBINS*WDIM];           // x + attn (fp32, residual)
__device__ __half g_zh [(size_t)BC*NBINS*WDIM];           // normalized acts (half)
__device__ __half g_qrh[(size_t)BC*NBINS*WDIM];           // rotated q==k (half)
__device__ __half g_vh [(size_t)BC*NBINS*WDIM];           // v (half)
__device__ __half g_ph [(size_t)BCH*WDIM*WDIM];           // softmax probs (half)
__device__ __half g_ath[(size_t)BC*NBINS*WDIM];           // attn back to (bc,g,w) half
__device__ __half g_hh [(size_t)BC*NBINS*4*WDIM];         // MLP hidden (half)
__device__ __half g_wqh[(size_t)CDIM*NBINS*NBINS];
__device__ __half g_woh[(size_t)CDIM*NBINS*NBINS];
__device__ __half g_w1h[(size_t)CDIM*4*NBINS*NBINS];
__device__ __half g_w2h[(size_t)CDIM*4*NBINS*NBINS];

// ---------------- fp32 -> fp16 bulk convert ----------------------------------
__global__ void f2h_kernel(const float* __restrict__ s, __half* __restrict__ d)
{
    size_t i = ((size_t)blockIdx.x * 256 + threadIdx.x) * 8;
    float4 v0 = *reinterpret_cast<const float4*>(s + i);
    float4 v1 = *reinterpret_cast<const float4*>(s + i + 4);
    __half2 h0 = __floats2half2_rn(v0.x, v0.y);
    __half2 h1 = __floats2half2_rn(v0.z, v0.w);
    __half2 h2 = __floats2half2_rn(v1.x, v1.y);
    __half2 h3 = __floats2half2_rn(v1.z, v1.w);
    uint4 o;
    o.x = *reinterpret_cast<uint32_t*>(&h0);
    o.y = *reinterpret_cast<uint32_t*>(&h1);
    o.z = *reinterpret_cast<uint32_t*>(&h2);
    o.w = *reinterpret_cast<uint32_t*>(&h3);
    *reinterpret_cast<uint4*>(d + i) = o;
}

// ---------------- frame-norm statistics ------------------------------------
__global__ void stats_kernel(const float* __restrict__ x,
                             float* __restrict__ meanOut, float* __restrict__ rstdOut)
{
    int bc = blockIdx.x;
    int wl = threadIdx.x & 63;
    int fg = threadIdx.x >> 6;
    int w  = blockIdx.y * 64 + wl;
    const float* xb = x + (size_t)bc * NBINS * WDIM + w;
    float s = 0.f, sq = 0.f;
    for (int f = fg; f < NBINS; f += 4) {
        float v = xb[(size_t)f * WDIM];
        s += v; sq += v * v;
    }
    __shared__ float ss[4][64], sv[4][64];
    ss[fg][wl] = s; sv[fg][wl] = sq;
    __syncthreads();
    if (fg == 0) {
        s  = ss[0][wl] + ss[1][wl] + ss[2][wl] + ss[3][wl];
        sq = sv[0][wl] + sv[1][wl] + sv[2][wl] + sv[3][wl];
        float m   = s * (1.0f / NBINS);
        float var = sq * (1.0f / NBINS) - m * m;
        meanOut[bc * WDIM + w] = m;
        rstdOut[bc * WDIM + w] = rsqrtf(var + FN_EPS);
    }
}

// ---------------- apply norm elementwise -> half -----------------------------
__global__ void normalize_kernel(const float* __restrict__ x,
                                 const float* __restrict__ mean, const float* __restrict__ rstd,
                                 const float* __restrict__ wgt,  const float* __restrict__ bias,
                                 __half* __restrict__ z)
{
    size_t idx = (size_t)blockIdx.x * 256 + threadIdx.x;
    int w  = (int)(idx & (WDIM - 1));
    int f  = (int)((idx >> 9) & (NBINS - 1));
    int bc = (int)(idx >> 19);
    int col = bc * WDIM + w;
    z[idx] = __float2half((x[idx] - mean[col]) * rstd[col] * wgt[f] + bias[f]);
}

// ---------------- RoPE + transpose -> half (bch,w,d) -------------------------
__global__ void rope_kernel(const float* __restrict__ y, const float* __restrict__ freqs,
                            __half* __restrict__ qr, __half* __restrict__ v)
{
    __shared__ float tile[32][33];
    int bc = blockIdx.z;
    int g0 = blockIdx.y * 32;
    int w0 = blockIdx.x * 32;
    int tx = threadIdx.x, ty = threadIdx.y;
    const float* yb = y + (size_t)bc * NBINS * WDIM;
    #pragma unroll
    for (int r = 0; r < 4; r++) {
        int gl = ty + r * 8;
        tile[gl][tx] = yb[(size_t)(g0 + gl) * WDIM + w0 + tx];
    }
    __syncthreads();
    int h  = g0 / HD;
    int d0 = g0 % HD;
    int d  = d0 + tx;
    __half* qb = qr + (size_t)(bc * NHEADS + h) * WDIM * HD;
    __half* vb = v  + (size_t)(bc * NHEADS + h) * WDIM * HD;
    float fr = (d0 == 0) ? freqs[d >> 1] : 0.f;
    #pragma unroll
    for (int r = 0; r < 4; r++) {
        int wl = ty + r * 8;
        int w  = w0 + wl;
        float val = tile[tx][wl];
        float o;
        if (d0 == 0) {
            float pv = tile[tx ^ 1][wl];
            float sn, cs;
            sincosf((float)w * fr, &sn, &cs);
            o = (d & 1) ? fmaf(val, cs,  pv * sn)
                        : fmaf(val, cs, -pv * sn);
        } else {
            o = val;
        }
        qb[(size_t)w * HD + d] = __float2half(o);
        vb[(size_t)w * HD + d] = __float2half(val);
    }
}

// ---------------- softmax over rows of 512 (fp32 in, half out) ---------------
__global__ void softmax_kernel(const float* __restrict__ s, __half* __restrict__ p)
{
    int row  = blockIdx.x * 8 + (threadIdx.x >> 5);
    int lane = threadIdx.x & 31;
    const float* pi = s + (size_t)row * WDIM;
    __half* po = p + (size_t)row * WDIM;
    float v[16];
    float mx = -1e30f;
    #pragma unroll
    for (int i = 0; i < 16; i++) { v[i] = pi[lane + i * 32]; mx = fmaxf(mx, v[i]); }
    #pragma unroll
    for (int o = 16; o > 0; o >>= 1) mx = fmaxf(mx, __shfl_xor_sync(0xffffffffu, mx, o));
    float sum = 0.f;
    #pragma unroll
    for (int i = 0; i < 16; i++) { v[i] = expf(v[i] - mx); sum += v[i]; }
    #pragma unroll
    for (int o = 16; o > 0; o >>= 1) sum += __shfl_xor_sync(0xffffffffu, sum, o);
    float inv = 1.0f / sum;
    #pragma unroll
    for (int i = 0; i < 16; i++) po[lane + i * 32] = __float2half(v[i] * inv);
}

// ---------------- (bch,w,d) fp32 -> (bc,g,w) half ----------------------------
__global__ void untranspose_kernel(const float* __restrict__ att, __half* __restrict__ out)
{
    __shared__ float tile[32][33];
    int bc = blockIdx.z;
    int g0 = blockIdx.y * 32;
    int w0 = blockIdx.x * 32;
    int h  = g0 / HD;
    int d0 = g0 % HD;
    const float* ab = att + (size_t)(bc * NHEADS + h) * WDIM * HD;
    int tx = threadIdx.x, ty = threadIdx.y;
    #pragma unroll
    for (int r = 0; r < 4; r++) {
        int wl = ty + r * 8;
        tile[wl][tx] = ab[(size_t)(w0 + wl) * HD + d0 + tx];
    }
    __syncthreads();
    __half* ob = out + (size_t)bc * NBINS * WDIM;
    #pragma unroll
    for (int r = 0; r < 4; r++) {
        int dl = ty + r * 8;
        ob[(size_t)(g0 + dl) * WDIM + w0 + tx] = __float2half(tile[tx][dl]);
    }
}

// ================= FP16 tensor-core GEMM, cp.async + ldmatrix ================
// C = alpha * A @ B (+residual | gelu->half). A,B fp16 in gmem.
// A: MxK row-major (batch = z % a_mod). B: KxN row-major, NxK when TRANSB.
// Block 128x128x32, 3-stage cp.async pipeline, 8 warps of 64x32, m16n8k16.
//
// Smem swizzles (byte offsets within an 8KB tile):
//  A / TRANSB-B ("row-major 64B rows"): r(0..127), k(0..31):
//    p=r>>1, c=((r&1)<<2)|(k>>3), off = p*128 + (c^(p&7))*16 + (k&7)*2
//  K-major B: k(0..31), n(0..127):
//    p=(k<<1)|(n>>6), off = p*128 + (((n>>3)&7)^(k&7))*16 + (n&7)*2

__device__ __forceinline__ uint32_t a_swz(int r, int k) {
    int p = r >> 1;
    int c = ((r & 1) << 2) | (k >> 3);
    return (uint32_t)(p * 128 + ((c ^ (p & 7)) * 16) + ((k & 7) << 1));
}
__device__ __forceinline__ uint32_t bk_swz(int k, int n) {
    int p = (k << 1) | (n >> 6);
    int c = ((n >> 3) & 7) ^ (k & 7);
    return (uint32_t)(p * 128 + c * 16 + ((n & 7) << 1));
}

__device__ __forceinline__ void cp16(uint32_t saddr, const void* g) {
    asm volatile("cp.async.cg.shared.global [%0], [%1], 16;" :: "r"(saddr), "l"(g));
}
__device__ __forceinline__ void ldsm4(uint32_t& r0, uint32_t& r1, uint32_t& r2,
                                      uint32_t& r3, uint32_t addr) {
    asm volatile("ldmatrix.sync.aligned.m8n8.x4.shared.b16 {%0,%1,%2,%3}, [%4];"
                 : "=r"(r0), "=r"(r1), "=r"(r2), "=r"(r3) : "r"(addr));
}
__device__ __forceinline__ void ldsm4t(uint32_t& r0, uint32_t& r1, uint32_t& r2,
                                       uint32_t& r3, uint32_t addr) {
    asm volatile("ldmatrix.sync.aligned.m8n8.x4.trans.shared.b16 {%0,%1,%2,%3}, [%4];"
                 : "=r"(r0), "=r"(r1), "=r"(r2), "=r"(r3) : "r"(addr));
}
__device__ __forceinline__ void mma_f16(float c[4], uint32_t a0, uint32_t a1,
                                        uint32_t a2, uint32_t a3,
                                        uint32_t b0, uint32_t b1) {
    asm volatile(
        "mma.sync.aligned.m16n8k16.row.col.f32.f16.f16.f32 "
        "{%0,%1,%2,%3},{%4,%5,%6,%7},{%8,%9},{%0,%1,%2,%3};"
        : "+f"(c[0]), "+f"(c[1]), "+f"(c[2]), "+f"(c[3])
        : "r"(a0), "r"(a1), "r"(a2), "r"(a3), "r"(b0), "r"(b1));
}

// EPI: 0 = alpha, fp32 out; 1 = +residual, fp32 out; 2 = gelu, half out
template<bool TRANSB, int EPI>
__global__ void __launch_bounds__(256, 2)
tc_gemm(const __half* __restrict__ Aall, const __half* __restrict__ Ball,
        void* __restrict__ Call, const float* __restrict__ ResAll,
        int M, int N, int K, int a_mod, float alpha)
{
    __shared__ __align__(128) unsigned char smraw[3 * 16384];
    const uint32_t smb = (uint32_t)__cvta_generic_to_shared(smraw);

    const int batch = blockIdx.z;
    const __half* A = Aall + (size_t)(batch % a_mod) * M * K;
    const __half* B = Ball + (size_t)batch * (size_t)K * N;

    const int tid  = threadIdx.x;
    const int m0   = blockIdx.y * 128;
    const int n0   = blockIdx.x * 128;
    const int nt   = K >> 5;
    const int lane = tid & 31;
    const int warp = tid >> 5;
    const int wm   = (warp & 1) * 64;
    const int wn   = (warp >> 1) * 32;

    // -------- per-thread cp.async source/dest precompute --------
    // A: chunk q = tid + j*256: r=q>>2, k0=(q&3)*8
    int aR[2], aK[2]; uint32_t aDst[2];
    #pragma unroll
    for (int j = 0; j < 2; j++) {
        int q = tid + j * 256;
        aR[j] = q >> 2; aK[j] = (q & 3) << 3;
        aDst[j] = a_swz(aR[j], aK[j]);
    }
    int bR[2], bK[2]; uint32_t bDst[2];
    #pragma unroll
    for (int j = 0; j < 2; j++) {
        int q = tid + j * 256;
        if (TRANSB) {
            bR[j] = q >> 2; bK[j] = (q & 3) << 3;
            bDst[j] = a_swz(bR[j], bK[j]);
        } else {
            int k = q >> 4, n = (q & 15) << 3;
            bR[j] = k; bK[j] = n;
            bDst[j] = bk_swz(k, n);
        }
    }

    auto issue = [&](int t, int s) {
        uint32_t sa = smb + s * 16384;
        uint32_t sb = sa + 8192;
        #pragma unroll
        for (int j = 0; j < 2; j++)
            cp16(sa + aDst[j], A + (size_t)(m0 + aR[j]) * K + (t << 5) + aK[j]);
        #pragma unroll
        for (int j = 0; j < 2; j++) {
            if (TRANSB) {
                cp16(sb + bDst[j], B + (size_t)(n0 + bR[j]) * K + (t << 5) + bK[j]);
            } else {
                int gn = (n0 + bK[j]) & (N - 1);   // N is power of 2; wrap (dup) pads
                cp16(sb + bDst[j], B + (size_t)((t << 5) + bR[j]) * N + gn);
            }
        }
    };

    // -------- fragment smem addresses (stage 0, kk = 0) --------
    uint32_t aAddr[4];
    #pragma unroll
    for (int mt = 0; mt < 4; mt++) {
        int r = wm + mt * 16 + (lane & 15);
        int k = (lane >> 4) << 3;
        aAddr[mt] = smb + a_swz(r, k);
    }
    uint32_t bAddr[2];
    #pragma unroll
    for (int j = 0; j < 2; j++) {
        if (TRANSB) {
            int n = wn + j * 16 + ((lane >> 4) << 3) + (lane & 7);
            int k = ((lane >> 3) & 1) << 3;
            bAddr[j] = smb + 8192 + a_swz(n, k);
        } else {
            int k = lane & 15;
            int n = wn + j * 16 + (lane >> 4) * 8;
            bAddr[j] = smb + 8192 + bk_swz(k, n);
        }
    }

    float acc[4][4][4];
    #pragma unroll
    for (int i = 0; i < 4; i++)
        #pragma unroll
        for (int j = 0; j < 4; j++)
            #pragma unroll
            for (int q = 0; q < 4; q++) acc[i][j][q] = 0.f;

    // -------- pipeline: prefetch 2 stages --------
    issue(0, 0); asm volatile("cp.async.commit_group;");
    issue(1, 1); asm volatile("cp.async.commit_group;");

    for (int t = 0; t < nt; t++) {
        asm volatile("cp.async.wait_group 1;");
        __syncthreads();
        // keep one commit per iteration (possibly empty) so wait_group 1 == stage t ready
        if (t + 2 < nt) issue(t + 2, (t + 2) % 3);
        asm volatile("cp.async.commit_group;");

        const uint32_t soff = (uint32_t)((t % 3) * 16384);
        #pragma unroll
        for (int kk = 0; kk < 2; kk++) {
            uint32_t a[4][4];
            uint32_t b[4][2];
            #pragma unroll
            for (int mt = 0; mt < 4; mt++) {
                uint32_t ad = (aAddr[mt] + soff) ^ (kk ? 32u : 0u);
                ldsm4(a[mt][0], a[mt][1], a[mt][2], a[mt][3], ad);
            }
            #pragma unroll
            for (int j = 0; j < 2; j++) {
                uint32_t bd;
                if (TRANSB) bd = (bAddr[j] + soff) ^ (kk ? 32u : 0u);
                else        bd = bAddr[j] + soff + (kk ? 4096u : 0u);
                if (TRANSB) ldsm4 (b[2*j][0], b[2*j][1], b[2*j+1][0], b[2*j+1][1], bd);
                else        ldsm4t(b[2*j][0], b[2*j][1], b[2*j+1][0], b[2*j+1][1], bd);
            }
            #pragma unroll
            for (int mt = 0; mt < 4; mt++)
                #pragma unroll
                for (int ntl = 0; ntl < 4; ntl++)
                    mma_f16(acc[mt][ntl],
                            a[mt][0], a[mt][1], a[mt][2], a[mt][3],
                            b[ntl][0], b[ntl][1]);
        }
    }

    // -------- epilogue --------
    const int lr = lane >> 2;
    const int lc = lane & 3;
    const float* Res = (EPI == 1) ? (ResAll + (size_t)batch * (size_t)M * N) : nullptr;
    float*  Cf = (float*)Call  + (EPI != 2 ? (size_t)batch * (size_t)M * N : 0);
    __half* Ch = (__half*)Call + (EPI == 2 ? (size_t)batch * (size_t)M * N : 0);

    #pragma unroll
    for (int mt = 0; mt < 4; mt++) {
        #pragma unroll
        for (int ntl = 0; ntl < 4; ntl++) {
            int col = n0 + wn + ntl * 8 + lc * 2;
            if (col >= N) continue;
            #pragma unroll
            for (int half = 0; half < 2; half++) {
                int row = m0 + wm + mt * 16 + lr + half * 8;
                float v0 = acc[mt][ntl][half * 2 + 0] * alpha;
                float v1 = acc[mt][ntl][half * 2 + 1] * alpha;
                if (EPI == 1) {
                    v0 += Res[(size_t)row * N + col];
                    v1 += Res[(size_t)row * N + col + 1];
                }
                if (EPI == 2) {
                    v0 = 0.5f * v0 * (1.0f + erff(v0 * 0.70710678118654752f));
                    v1 = 0.5f * v1 * (1.0f + erff(v1 * 0.70710678118654752f));
                    __half2 h = __floats2half2_rn(v0, v1);
                    *reinterpret_cast<__half2*>(Ch + (size_t)row * N + col) = h;
                } else {
                    *reinterpret_cast<float2*>(Cf + (size_t)row * N + col) =
                        make_float2(v0, v1);
                }
            }
        }
    }
}

// ---------------- launcher ----------------------------------------------------
extern "C" void kernel_launch(void* const* d_in, const int* in_sizes, int n_in,
                              void* d_out, int out_size)
{
    (void)in_sizes; (void)n_in; (void)out_size;
    const float* x      = (const float*)d_in[0];
    const float* n1w    = (const float*)d_in[1];
    const float* n1b    = (const float*)d_in[2];
    const float* freqs  = (const float*)d_in[3];
    const float* q_w    = (const float*)d_in[4];
    const float* out_w  = (const float*)d_in[5];
    const float* n2w    = (const float*)d_in[6];
    const float* n2b    = (const float*)d_in[7];
    const float* lin1_w = (const float*)d_in[8];
    const float* lin2_w = (const float*)d_in[9];
    float* out = (float*)d_out;

    float  *p_mean, *p_rstd, *p_y, *p_s, *p_att, *p_x1;
    __half *p_zh, *p_qrh, *p_vh, *p_ph, *p_ath, *p_hh, *p_wqh, *p_woh, *p_w1h, *p_w2h;
    cudaGetSymbolAddress((void**)&p_mean, g_mean);
    cudaGetSymbolAddress((void**)&p_rstd, g_rstd);
    cudaGetSymbolAddress((void**)&p_y,   g_y);
    cudaGetSymbolAddress((void**)&p_s,   g_s);
    cudaGetSymbolAddress((void**)&p_att, g_att);
    cudaGetSymbolAddress((void**)&p_x1,  g_x1);
    cudaGetSymbolAddress((void**)&p_zh,  g_zh);
    cudaGetSymbolAddress((void**)&p_qrh, g_qrh);
    cudaGetSymbolAddress((void**)&p_vh,  g_vh);
    cudaGetSymbolAddress((void**)&p_ph,  g_ph);
    cudaGetSymbolAddress((void**)&p_ath, g_ath);
    cudaGetSymbolAddress((void**)&p_hh,  g_hh);
    cudaGetSymbolAddress((void**)&p_wqh, g_wqh);
    cudaGetSymbolAddress((void**)&p_woh, g_woh);
    cudaGetSymbolAddress((void**)&p_w1h, g_w1h);
    cudaGetSymbolAddress((void**)&p_w2h, g_w2h);

    // weight conversion fp32 -> fp16
    f2h_kernel<<<CDIM*NBINS*NBINS/2048, 256>>>(q_w,    p_wqh);
    f2h_kernel<<<CDIM*NBINS*NBINS/2048, 256>>>(out_w,  p_woh);
    f2h_kernel<<<CDIM*4*NBINS*NBINS/2048, 256>>>(lin1_w, p_w1h);
    f2h_kernel<<<CDIM*4*NBINS*NBINS/2048, 256>>>(lin2_w, p_w2h);

    dim3 statsGrid(BC, WDIM / 64);

    // norm1
    stats_kernel<<<statsGrid, 256>>>(x, p_mean, p_rstd);
    normalize_kernel<<<32768, 256>>>(x, p_mean, p_rstd, n1w, n1b, p_zh);

    // q projection (M=1024, N=512, K=1024) -> fp32 y
    tc_gemm<false, 0><<<dim3(4, 8, BC), 256>>>(p_wqh, p_zh, p_y, nullptr,
                                               1024, 512, 1024, CDIM, 1.0f);

    // RoPE + head transpose -> half qr, v
    rope_kernel<<<dim3(16, 32, BC), dim3(32, 8)>>>(p_y, freqs, p_qrh, p_vh);

    // scores = QR @ QR^T / 32  (M=512, N=512, K=64, batch 256) -> fp32 s
    tc_gemm<true, 0><<<dim3(4, 4, BCH), 256>>>(p_qrh, p_qrh, p_s, nullptr,
                                               512, 512, 64, BCH, 0.03125f);

    // softmax -> half probs
    softmax_kernel<<<BCH * WDIM / 8, 256>>>(p_s, p_ph);

    // attn = P @ V  (M=512, N=64, K=512, batch 256) -> fp32 att
    tc_gemm<false, 0><<<dim3(1, 4, BCH), 256>>>(p_ph, p_vh, p_att, nullptr,
                                                512, 64, 512, BCH, 1.0f);

    // back to (bc,g,w) half
    untranspose_kernel<<<dim3(16, 32, BC), dim3(32, 8)>>>(p_att, p_ath);

    // out projection + residual -> fp32 x1
    tc_gemm<false, 1><<<dim3(4, 8, BC), 256>>>(p_woh, p_ath, p_x1, x,
                                               1024, 512, 1024, CDIM, 1.0f);

    // norm2
    stats_kernel<<<statsGrid, 256>>>(p_x1, p_mean, p_rstd);
    normalize_kernel<<<32768, 256>>>(p_x1, p_mean, p_rstd, n2w, n2b, p_zh);

    // MLP lin1 + gelu -> half h  (M=4096, N=512, K=1024)
    tc_gemm<false, 2><<<dim3(4, 32, BC), 256>>>(p_w1h, p_zh, p_hh, nullptr,
                                                4096, 512, 1024, CDIM, 1.0f);

    // MLP lin2 + residual -> out (M=1024, N=512, K=4096)
    tc_gemm<false, 1><<<dim3(4, 8, BC), 256>>>(p_w2h, p_hh, out, p_x1,
                                               1024, 512, 4096, CDIM, 1.0f);
}